// round 14
// baseline (speedup 1.0000x reference)
#include <cuda_runtime.h>
#include <cuda_bf16.h>
#include <cstdint>
#include <math.h>

// ---------------------------------------------------------------------------
// Problem constants
// ---------------------------------------------------------------------------
#define BATCH   8192
#define NPG     32
#define EPG     64
#define NNODES  (BATCH * NPG)      // 262144
#define NEDGES  (BATCH * EPG)      // 524288
#define CELLD   908
#define BN_EPS  1e-5f

// BN stats offsets
#define OFF_CE1 0      // 516
#define OFF_CE2 516    // 256
#define OFF_CE3 772    // 128
#define OFF_G1A 900    // 128 (mrs slot only)
#define OFF_G1B 1028   // 128
#define OFF_G2A 1156   // 128
#define OFF_G2B 1284   // 128
#define OFF_D1  1412   // 128
#define OFF_F1  1540   // 128
#define OFF_F2  1668   // 64
#define STATS_N 1732
#define OFF_F1CAT 1732 // mrs-only: 256 entries (ce3 stats | identity)
#define MRS_N   1988
#define G1B_N   (32 * 128)

// Weight slab-image: per (ntile,kslab) block = 128 rows x 40 u16 (pitch 80B) = 10240B
#define IMG_CE1 0
#define IMG_CE2 742400
#define IMG_CE3 916480
#define IMG_G12 957440
#define IMG_G21 977920
#define IMG_G22 998400
#define IMG_D1  1018880
#define IMG_D2  1039360
#define IMG_F1  1059840
#define IMG_F2  1100800
#define IMG_TOTAL 1121280

// ---------------------------------------------------------------------------
// Static device scratch
// ---------------------------------------------------------------------------
__device__ float  g_A [NNODES * 128];
__device__ float  g_Bf[NNODES * 128];
__device__ float  g_c1[BATCH * 516];
__device__ float  g_c2[BATCH * 256];
__device__ float  g_z [BATCH * 256];
__device__ float  g_p [BATCH * 128];
__device__ float  g_q [BATCH * 128];
__device__ float  g_f2[BATCH * 64];
__device__ double g_stats[2 * STATS_N + 2 * G1B_N];
__device__ float2 g_mrs[MRS_N];
__device__ __align__(16) __nv_bfloat16 g_whi[IMG_TOTAL];
__device__ __align__(16) __nv_bfloat16 g_wlo[IMG_TOTAL];

// ---------------------------------------------------------------------------
// Streams/events for fork-join capture (created pre-main; no allocs in launch)
// ---------------------------------------------------------------------------
static cudaStream_t g_s2;
static cudaEvent_t  g_ev1, g_ev2, g_ev3;
static struct StreamInit {
    StreamInit() {
        cudaStreamCreateWithFlags(&g_s2, cudaStreamNonBlocking);
        cudaEventCreateWithFlags(&g_ev1, cudaEventDisableTiming);
        cudaEventCreateWithFlags(&g_ev2, cudaEventDisableTiming);
        cudaEventCreateWithFlags(&g_ev3, cudaEventDisableTiming);
    }
} g_streaminit;

// ---------------------------------------------------------------------------
// PTX helpers
// ---------------------------------------------------------------------------
__device__ __forceinline__ void mma16816(float* c, const uint32_t* a, const uint32_t* b) {
    asm volatile(
        "mma.sync.aligned.m16n8k16.row.col.f32.bf16.bf16.f32 "
        "{%0,%1,%2,%3}, {%4,%5,%6,%7}, {%8,%9}, {%0,%1,%2,%3};"
        : "+f"(c[0]), "+f"(c[1]), "+f"(c[2]), "+f"(c[3])
        : "r"(a[0]), "r"(a[1]), "r"(a[2]), "r"(a[3]), "r"(b[0]), "r"(b[1]));
}

__device__ __forceinline__ void ldsm4(uint32_t* r, uint32_t addr) {
    asm volatile("ldmatrix.sync.aligned.m8n8.x4.shared.b16 {%0,%1,%2,%3}, [%4];"
                 : "=r"(r[0]), "=r"(r[1]), "=r"(r[2]), "=r"(r[3]) : "r"(addr));
}

__device__ __forceinline__ uint32_t s2u(const void* p) {
    uint32_t a;
    asm("{ .reg .u64 t; cvta.to.shared.u64 t, %1; cvt.u32.u64 %0, t; }"
        : "=r"(a) : "l"(p));
    return a;
}

__device__ __forceinline__ void cpasync16(uint32_t dst, const void* src) {
    asm volatile("cp.async.cg.shared.global [%0], [%1], 16;"
                 :: "r"(dst), "l"(src) : "memory");
}
#define CP_COMMIT() asm volatile("cp.async.commit_group;" ::: "memory")
#define CP_WAIT0()  asm volatile("cp.async.wait_group 0;"  ::: "memory")

__device__ __forceinline__ uint32_t packbf(float a, float b) {
    __nv_bfloat16 ha = __float2bfloat16(a), hb = __float2bfloat16(b);
    return (uint32_t)__bfloat16_as_ushort(ha) |
           ((uint32_t)__bfloat16_as_ushort(hb) << 16);
}

// order-preserving float<->uint for atomicMax
__device__ __forceinline__ uint32_t encf(float f) {
    uint32_t b = __float_as_uint(f);
    return (b & 0x80000000u) ? ~b : (b | 0x80000000u);
}
__device__ __forceinline__ float decf(uint32_t u) {
    return (u & 0x80000000u) ? __uint_as_float(u ^ 0x80000000u) : __uint_as_float(~u);
}

__device__ __forceinline__ float2 mrs_of(const double* sum, const double* sq,
                                         int c, float invM) {
    float m = (float)sum[c] * invM;
    float v = (float)sq[c] * invM - m * m;
    return make_float2(m, rsqrtf(v + BN_EPS));
}

// ---------------------------------------------------------------------------
// Fused weight conversion (unchanged)
// ---------------------------------------------------------------------------
__global__ __launch_bounds__(256)
void wconv_all(const float* w0, const float* w1, const float* w2, const float* w3,
               const float* w4, const float* w5, const float* w6, const float* w7,
               const float* w8, const float* w9,
               __nv_bfloat16* __restrict__ hi, __nv_bfloat16* __restrict__ lo)
{
    constexpr int WK[10]   = {908, 516, 256, 128, 128, 128, 128, 128, 256, 128};
    constexpr int WN[10]   = {516, 256, 128, 128, 128, 128, 128, 128, 128, 64};
    constexpr int WNS[10]  = {29, 17, 8, 4, 4, 4, 4, 4, 8, 4};
    constexpr int WCUM[11] = {0, 145, 179, 187, 191, 195, 199, 203, 207, 215, 219};
    constexpr int WIOF[10] = {IMG_CE1, IMG_CE2, IMG_CE3, IMG_G12, IMG_G21,
                              IMG_G22, IMG_D1, IMG_D2, IMG_F1, IMG_F2};

    __shared__ float tile[32][129];

    int blk = blockIdx.x;
    int wi = 0;
    #pragma unroll
    for (int i = 0; i < 10; i++)
        if (blk >= WCUM[i] && blk < WCUM[i + 1]) wi = i;
    int local = blk - WCUM[wi];
    int nslab = WNS[wi];
    int nt = local / nslab, s = local - nt * nslab;
    int K = WK[wi], N = WN[wi];

    const float* W;
    switch (wi) {
        case 0: W = w0; break; case 1: W = w1; break; case 2: W = w2; break;
        case 3: W = w3; break; case 4: W = w4; break; case 5: W = w5; break;
        case 6: W = w6; break; case 7: W = w7; break; case 8: W = w8; break;
        default: W = w9; break;
    }

    int tid = threadIdx.x;
    int nc = tid & 127, kq = tid >> 7;
    #pragma unroll
    for (int i = 0; i < 16; i++) {
        int k = kq + i * 2;
        int gk = s * 32 + k, gn = nt * 128 + nc;
        float v = (gk < K && gn < N) ? W[(size_t)gk * N + gn] : 0.f;
        tile[k][nc] = v;
    }
    __syncthreads();

    char* hb = (char*)(hi + WIOF[wi]) + (size_t)local * 10240;
    char* lb = (char*)(lo + WIOF[wi]) + (size_t)local * 10240;
    #pragma unroll
    for (int it = 0; it < 2; it++) {
        int idx = tid + it * 256;
        int n = idx >> 2, q = idx & 3;
        uint32_t h[4], l[4];
        #pragma unroll
        for (int j = 0; j < 4; j++) {
            float f0 = tile[q * 8 + 2 * j][n];
            float f1 = tile[q * 8 + 2 * j + 1][n];
            float h0 = __bfloat162float(__float2bfloat16(f0));
            float h1 = __bfloat162float(__float2bfloat16(f1));
            h[j] = packbf(f0, f1);
            l[j] = packbf(f0 - h0, f1 - h1);
        }
        *(uint4*)(hb + n * 80 + q * 16) = make_uint4(h[0], h[1], h[2], h[3]);
        *(uint4*)(lb + n * 80 + q * 16) = make_uint4(l[0], l[1], l[2], l[3]);
    }
}

// ---------------------------------------------------------------------------
// Templated fused tensor-core GEMM (mma.sync bf16 split-3, fp32 accum):
//   C = EPI_ACT( IN_ACT(BN_lut(A)) @ W + bias )
//   STAT_PRE: stats over relu(C);  POOL: per-graph max -> pmax, no C store
//   AGGE: GIN aggregation fused into EPILOGUE via (I+Adj)(yW) = ((I+Adj)y)W
// A loads use register prefetch distance 2 (two ping-pong register sets).
// IN_ACT: 0 none, 1 BN->relu, 2 BN->elu, 3 relu->BN
// ---------------------------------------------------------------------------
#define TG_SMEM 81920

template<int IN_ACT, int EPI_ACT, int STAT_PRE, int POOL, int AGGE>
__global__ __launch_bounds__(256, 2)
void tgemm(const float* __restrict__ A, int lda, int Korig, int nslab,
           const __nv_bfloat16* __restrict__ Whi, const __nv_bfloat16* __restrict__ Wlo,
           const float* __restrict__ bias,
           float* __restrict__ C, int ldc, int N,
           const float2* __restrict__ mrsIn,
           double* __restrict__ stSum, double* __restrict__ stSq,
           float* __restrict__ pmax,
           const int* __restrict__ srcE, const int* __restrict__ dstE)
{
    extern __shared__ char dynsm[];
    __shared__ float ssum[128], ssq[128];
    __shared__ uint32_t pmS[POOL ? 512 : 1];
    __shared__ int lsE[AGGE ? 256 : 1], ldE[AGGE ? 256 : 1];

    const int tid = threadIdx.x;
    const int wid = tid >> 5, lane = tid & 31;
    const int mt = blockIdx.y, ntile = blockIdx.x;
    const int bn0 = ntile * 128;

    const float* Ab = A + (size_t)mt * 128 * lda;
    const char* BHall = (const char*)Whi + (size_t)ntile * nslab * 10240;
    const char* BLall = (const char*)Wlo + (size_t)ntile * nslab * 10240;

    const uint32_t smu = s2u(dynsm);
    const int wm = (wid >> 2) * 64, wn = (wid & 3) * 32;

    if (AGGE) {
        lsE[tid] = srcE[mt * 256 + tid] & (NPG - 1);
        ldE[tid] = dstE[mt * 256 + tid] & (NPG - 1);
    }

    float acc[4][4][4];
    #pragma unroll
    for (int a = 0; a < 4; a++)
        #pragma unroll
        for (int b = 0; b < 4; b++)
            #pragma unroll
            for (int c = 0; c < 4; c++) acc[a][b][c] = 0.f;

    float4 av[2][4];   // two register sets: A prefetch distance 2

    auto bload = [&](int s) {
        uint32_t st = (uint32_t)(s & 1) * 10240u;
        uint32_t dh = smu + 40960 + st, dl = smu + 61440 + st;
        const char* sh = BHall + (size_t)s * 10240;
        const char* sl = BLall + (size_t)s * 10240;
        #pragma unroll
        for (int i = tid; i < 640; i += 256) {
            cpasync16(dh + i * 16, sh + i * 16);
            cpasync16(dl + i * 16, sl + i * 16);
        }
        CP_COMMIT();
    };

    auto gload = [&](int s, int rs) {
        int k0 = s * 32;
        #pragma unroll
        for (int j = 0; j < 4; j++) {
            int f = tid + 256 * j;
            int r = f >> 3, c4 = f & 7;
            int kc = k0 + c4 * 4;
            const float* ap = Ab + (size_t)r * lda + kc;
            if (kc + 3 < Korig) {
                av[rs][j] = *(const float4*)ap;
            } else {
                av[rs][j].x = (kc + 0 < Korig) ? ap[0] : 0.f;
                av[rs][j].y = (kc + 1 < Korig) ? ap[1] : 0.f;
                av[rs][j].z = (kc + 2 < Korig) ? ap[2] : 0.f;
                av[rs][j].w = (kc + 3 < Korig) ? ap[3] : 0.f;
            }
        }
    };

    auto convstore = [&](int s, int rs) {
        uint32_t st = (uint32_t)(s & 1) * 10240u;
        char* AH = dynsm + st;
        char* AL = dynsm + 20480 + st;
        int k0 = s * 32;
        #pragma unroll
        for (int j = 0; j < 4; j++) {
            int f = tid + 256 * j;
            int r = f >> 3, c4 = f & 7;
            float4 v = av[rs][j];
            if (IN_ACT != 0) {
                int kc = k0 + c4 * 4;
                float2 p0 = mrsIn[kc + 0], p1 = mrsIn[kc + 1];
                float2 p2 = mrsIn[kc + 2], p3 = mrsIn[kc + 3];
                if (IN_ACT == 3) {
                    v.x = (fmaxf(v.x, 0.f) - p0.x) * p0.y;
                    v.y = (fmaxf(v.y, 0.f) - p1.x) * p1.y;
                    v.z = (fmaxf(v.z, 0.f) - p2.x) * p2.y;
                    v.w = (fmaxf(v.w, 0.f) - p3.x) * p3.y;
                } else {
                    v.x = (v.x - p0.x) * p0.y;
                    v.y = (v.y - p1.x) * p1.y;
                    v.z = (v.z - p2.x) * p2.y;
                    v.w = (v.w - p3.x) * p3.y;
                    if (IN_ACT == 1) {
                        v.x = fmaxf(v.x, 0.f); v.y = fmaxf(v.y, 0.f);
                        v.z = fmaxf(v.z, 0.f); v.w = fmaxf(v.w, 0.f);
                    } else if (IN_ACT == 2) {
                        v.x = (v.x > 0.f) ? v.x : expm1f(v.x);
                        v.y = (v.y > 0.f) ? v.y : expm1f(v.y);
                        v.z = (v.z > 0.f) ? v.z : expm1f(v.z);
                        v.w = (v.w > 0.f) ? v.w : expm1f(v.w);
                    }
                }
            }
            float hx = __bfloat162float(__float2bfloat16(v.x));
            float hy = __bfloat162float(__float2bfloat16(v.y));
            float hz = __bfloat162float(__float2bfloat16(v.z));
            float hw = __bfloat162float(__float2bfloat16(v.w));
            uint2 h2, l2;
            h2.x = packbf(v.x, v.y);  h2.y = packbf(v.z, v.w);
            l2.x = packbf(v.x - hx, v.y - hy);
            l2.y = packbf(v.z - hz, v.w - hw);
            uint32_t off = (uint32_t)(r * 80 + c4 * 8);
            *(uint2*)(AH + off) = h2;
            *(uint2*)(AL + off) = l2;
        }
    };

    auto mma_slab = [&](int s) {
        uint32_t st = (uint32_t)(s & 1) * 10240u;
        uint32_t AHb = smu + st, ALb = smu + 20480 + st;
        uint32_t BHb = smu + 40960 + st, BLb = smu + 61440 + st;
        #pragma unroll
        for (int kk = 0; kk < 2; kk++) {
            uint32_t bh[4][2], bl[4][2];
            #pragma unroll
            for (int ni2 = 0; ni2 < 2; ni2++) {
                int n0 = wn + ni2 * 16 + ((lane >> 4) << 3) + (lane & 7);
                uint32_t off = (uint32_t)(n0 * 40 + kk * 16 + ((lane >> 3) & 1) * 8) * 2;
                uint32_t t4[4];
                ldsm4(t4, BHb + off);
                bh[2 * ni2][0] = t4[0]; bh[2 * ni2][1] = t4[1];
                bh[2 * ni2 + 1][0] = t4[2]; bh[2 * ni2 + 1][1] = t4[3];
                ldsm4(t4, BLb + off);
                bl[2 * ni2][0] = t4[0]; bl[2 * ni2][1] = t4[1];
                bl[2 * ni2 + 1][0] = t4[2]; bl[2 * ni2 + 1][1] = t4[3];
            }
            #pragma unroll
            for (int mi = 0; mi < 4; mi++) {
                int row = wm + mi * 16 + (lane & 15);
                uint32_t off = (uint32_t)(row * 40 + kk * 16 + (lane >> 4) * 8) * 2;
                uint32_t ah[4], al[4];
                ldsm4(ah, AHb + off);
                ldsm4(al, ALb + off);
                #pragma unroll
                for (int ni = 0; ni < 4; ni++) {
                    mma16816(acc[mi][ni], ah, bh[ni]);
                    mma16816(acc[mi][ni], ah, bl[ni]);
                    mma16816(acc[mi][ni], al, bh[ni]);
                }
            }
        }
    };

    // ---- pipelined mainloop (A prefetch distance 2) ----
    bload(0);
    gload(0, 0);
    convstore(0, 0);
    if (nslab > 1) gload(1, 1);
    CP_WAIT0();
    __syncthreads();
    for (int s = 0; s < nslab; s++) {
        bool more = (s + 1 < nslab);
        if (more) bload(s + 1);
        if (s + 2 < nslab) gload(s + 2, s & 1);
        mma_slab(s);
        if (more) { convstore(s + 1, (s + 1) & 1); CP_WAIT0(); }
        __syncthreads();
    }

    // ---- epilogue ----
    bool hasStats = (stSum != nullptr);
    if (hasStats && tid < 128) { ssum[tid] = 0.f; ssq[tid] = 0.f; }
    if (POOL) { pmS[tid] = 0u; pmS[tid + 256] = 0u; }
    __syncthreads();

    if (AGGE) {
        // out = u + Adj.u + bias, u = raw GEMM result; 2 phases of 64 rows
        float* u2 = (float*)dynsm;              // 64 x 129 floats
        float* ag = (float*)(dynsm + 33024);    // 64 x 129 floats
        const int gph = tid >> 7;               // graph within phase (0/1)
        const int cc  = tid & 127;
        const float bv = bias[cc];
        #pragma unroll
        for (int ph = 0; ph < 2; ph++) {
            if ((wid >> 2) == ph) {
                #pragma unroll
                for (int ni = 0; ni < 4; ni++) {
                    int lc0 = wn + ni * 8 + 2 * (lane & 3);
                    #pragma unroll
                    for (int mi = 0; mi < 4; mi++) {
                        int lr = mi * 16 + (lane >> 2);
                        u2[lr * 129 + lc0]           = acc[mi][ni][0];
                        u2[lr * 129 + lc0 + 1]       = acc[mi][ni][1];
                        u2[(lr + 8) * 129 + lc0]     = acc[mi][ni][2];
                        u2[(lr + 8) * 129 + lc0 + 1] = acc[mi][ni][3];
                    }
                }
            }
            __syncthreads();
            int rb = gph * 32;
            #pragma unroll 4
            for (int r = 0; r < 32; r++) ag[(rb + r) * 129 + cc] = 0.f;
            int eb = (ph * 2 + gph) * 64;
            for (int e = 0; e < 64; e++)
                ag[(rb + ldE[eb + e]) * 129 + cc] += u2[(rb + lsE[eb + e]) * 129 + cc];
            float s1 = 0.f, s2 = 0.f;
            #pragma unroll 4
            for (int r = 0; r < 32; r++) {
                float o = u2[(rb + r) * 129 + cc] + ag[(rb + r) * 129 + cc] + bv;
                C[(size_t)(mt * 128 + ph * 64 + rb + r) * ldc + cc] = o;
                s1 += o; s2 += o * o;
            }
            atomicAdd(&ssum[cc], s1);
            atomicAdd(&ssq[cc], s2);
            __syncthreads();
        }
    } else {
        #pragma unroll
        for (int ni = 0; ni < 4; ni++) {
            float ps0 = 0.f, ps1 = 0.f, pq0 = 0.f, pq1 = 0.f;
            int lc0 = wn + ni * 8 + 2 * (lane & 3);
            int gc0 = bn0 + lc0;
            float b0v = (gc0 < N) ? bias[gc0] : 0.f;
            float b1v = (gc0 + 1 < N) ? bias[gc0 + 1] : 0.f;
            #pragma unroll
            for (int mi = 0; mi < 4; mi++) {
                float v00 = acc[mi][ni][0] + b0v, v01 = acc[mi][ni][1] + b1v;
                float v10 = acc[mi][ni][2] + b0v, v11 = acc[mi][ni][3] + b1v;
                int lr0 = wm + mi * 16 + (lane >> 2);
                if (hasStats) {
                    float s00 = STAT_PRE ? fmaxf(v00, 0.f) : v00;
                    float s01 = STAT_PRE ? fmaxf(v01, 0.f) : v01;
                    float s10 = STAT_PRE ? fmaxf(v10, 0.f) : v10;
                    float s11 = STAT_PRE ? fmaxf(v11, 0.f) : v11;
                    ps0 += s00 + s10;  ps1 += s01 + s11;
                    pq0 += s00 * s00 + s10 * s10;
                    pq1 += s01 * s01 + s11 * s11;
                }
                if (POOL) {
                    atomicMax(&pmS[(lr0 >> 5) * 128 + lc0],           encf(v00));
                    atomicMax(&pmS[(lr0 >> 5) * 128 + lc0 + 1],       encf(v01));
                    atomicMax(&pmS[((lr0 + 8) >> 5) * 128 + lc0],     encf(v10));
                    atomicMax(&pmS[((lr0 + 8) >> 5) * 128 + lc0 + 1], encf(v11));
                } else if (gc0 < N) {
                    float o00 = v00, o01 = v01, o10 = v10, o11 = v11;
                    if (EPI_ACT == 1) {
                        o00 = fmaxf(o00, 0.f); o01 = fmaxf(o01, 0.f);
                        o10 = fmaxf(o10, 0.f); o11 = fmaxf(o11, 0.f);
                    }
                    int r0 = mt * 128 + lr0;
                    *(float2*)&C[(size_t)r0 * ldc + gc0]       = make_float2(o00, o01);
                    *(float2*)&C[(size_t)(r0 + 8) * ldc + gc0] = make_float2(o10, o11);
                }
            }
            if (hasStats) {
                #pragma unroll
                for (int off = 16; off >= 4; off >>= 1) {
                    ps0 += __shfl_xor_sync(0xffffffffu, ps0, off);
                    ps1 += __shfl_xor_sync(0xffffffffu, ps1, off);
                    pq0 += __shfl_xor_sync(0xffffffffu, pq0, off);
                    pq1 += __shfl_xor_sync(0xffffffffu, pq1, off);
                }
                if (lane < 4) {
                    int lc = wn + ni * 8 + 2 * lane;
                    atomicAdd(&ssum[lc], ps0);     atomicAdd(&ssq[lc], pq0);
                    atomicAdd(&ssum[lc + 1], ps1); atomicAdd(&ssq[lc + 1], pq1);
                }
            }
        }
    }
    __syncthreads();
    if (hasStats && tid < 128 && bn0 + tid < N) {
        atomicAdd(&stSum[bn0 + tid], (double)ssum[tid]);
        atomicAdd(&stSq[bn0 + tid],  (double)ssq[tid]);
    }
    if (POOL) {
        #pragma unroll
        for (int i = tid; i < 512; i += 256) {
            int g = mt * 4 + (i >> 7);
            pmax[(size_t)g * 128 + (i & 127)] = decf(pmS[i]);
        }
    }
}

// ---------------------------------------------------------------------------
// BN helper kernels
// ---------------------------------------------------------------------------
__global__ void init_misc(double* stats, float2* ident) {
    int i = blockIdx.x * blockDim.x + threadIdx.x;
    if (i < 2 * STATS_N + 2 * G1B_N) stats[i] = 0.0;
    if (i < 128) ident[i] = make_float2(0.f, 1.f);
}

__global__ void bn_finalize(const double* __restrict__ sum, const double* __restrict__ sumsq,
                            float2* __restrict__ mrs, int C, int M)
{
    int c = blockIdx.x * blockDim.x + threadIdx.x;
    if (c >= C) return;
    double m = sum[c] / (double)M;
    double v = sumsq[c] / (double)M - m * m;
    mrs[c] = make_float2((float)m, rsqrtf((float)v + BN_EPS));
}

__global__ void bn_finalize_g1(const double* __restrict__ bsum,
                               const double* __restrict__ bsq,
                               float2* __restrict__ mrs)
{
    int c = threadIdx.x;
    double s = 0.0, q = 0.0;
    #pragma unroll
    for (int b = 0; b < 32; b++) {
        s += bsum[b * 128 + c];
        q += bsq[b * 128 + c];
    }
    double m = s / (double)NNODES;
    double v = q / (double)NNODES - m * m;
    mrs[c] = make_float2((float)m, rsqrtf((float)v + BN_EPS));
}

// ---------------------------------------------------------------------------
// Graph kernels
// ---------------------------------------------------------------------------
__global__ void gin1_fused(const float* __restrict__ X,
                           const int* __restrict__ src, const int* __restrict__ dst,
                           const float* __restrict__ W, const float* __restrict__ b,
                           float* __restrict__ out,
                           double* __restrict__ bsum, double* __restrict__ bsq)
{
    __shared__ float xs[NPG][9];
    __shared__ float h0[NPG][9];
    __shared__ float Ws[9][128];
    __shared__ float bsh[128];
    __shared__ int   ls[EPG], ld[EPG];
    int g = blockIdx.x;
    int t = threadIdx.x;
    for (int i = t; i < NPG * 9; i += 128) {
        xs[i / 9][i % 9] = X[(size_t)g * NPG * 9 + i];
        h0[i / 9][i % 9] = 0.f;
    }
    if (t < EPG) {
        ls[t] = src[g * EPG + t] & (NPG - 1);
        ld[t] = dst[g * EPG + t] & (NPG - 1);
    }
    for (int i = t; i < 9 * 128; i += 128) Ws[i / 128][i % 128] = W[i];
    bsh[t] = b[t];
    __syncthreads();
    // parallel edge aggregation: 576 (edge, feature) items over 128 threads
    for (int i = t; i < EPG * 9; i += 128) {
        int e = i / 9, c = i - e * 9;
        atomicAdd(&h0[ld[e]][c], xs[ls[e]][c]);
    }
    __syncthreads();
    for (int i = t; i < NPG * 9; i += 128) h0[i / 9][i % 9] += xs[i / 9][i % 9];
    __syncthreads();
    float s1 = 0.f, s2 = 0.f;
    for (int r = 0; r < NPG; r++) {
        float acc = bsh[t];
        #pragma unroll
        for (int k = 0; k < 9; k++) acc += h0[r][k] * Ws[k][t];
        out[((size_t)g * NPG + r) * 128 + t] = acc;
        s1 += acc; s2 += acc * acc;
    }
    int bkt = (g & 31) * 128 + t;
    atomicAdd(&bsum[bkt], (double)s1);
    atomicAdd(&bsq[bkt],  (double)s2);
}

// y[i] = dot(elu(BN(Z[i,:])), w) + b; BN finalize inline from sums
__global__ void final_dot(const float* __restrict__ Z,
                          const double* __restrict__ sum, const double* __restrict__ sq,
                          const float* __restrict__ w, const float* __restrict__ b,
                          float* __restrict__ y, int Bn)
{
    int warp = (blockIdx.x * blockDim.x + threadIdx.x) >> 5;
    int lane = threadIdx.x & 31;
    if (warp >= Bn) return;
    float invM = 1.f / (float)BATCH;
    float2 p0 = mrs_of(sum, sq, lane, invM);
    float2 p1 = mrs_of(sum, sq, 32 + lane, invM);
    float x0 = (Z[(size_t)warp * 64 + lane]      - p0.x) * p0.y;
    float x1 = (Z[(size_t)warp * 64 + 32 + lane] - p1.x) * p1.y;
    x0 = (x0 > 0.f) ? x0 : expm1f(x0);
    x1 = (x1 > 0.f) ? x1 : expm1f(x1);
    float s = x0 * w[lane] + x1 * w[32 + lane];
    #pragma unroll
    for (int o = 16; o; o >>= 1) s += __shfl_down_sync(0xffffffffu, s, o);
    if (lane == 0) y[warp] = s + b[0];
}

// ---------------------------------------------------------------------------
// Host side
// ---------------------------------------------------------------------------
template<int IA, int EA, int SP, int PL, int AG>
static inline void run_tg(cudaStream_t st, const float* A, int lda, int Korig, int nslab,
                          const __nv_bfloat16* wh, const __nv_bfloat16* wl,
                          const float* bias, float* C, int ldc, int N,
                          const float2* mrs, double* ss, double* sq2,
                          float* pmax, const int* srcE, const int* dstE, int M)
{
    cudaFuncSetAttribute(tgemm<IA, EA, SP, PL, AG>,
                         cudaFuncAttributeMaxDynamicSharedMemorySize, TG_SMEM);
    dim3 g((N + 127) / 128, M / 128);
    tgemm<IA, EA, SP, PL, AG><<<g, 256, TG_SMEM, st>>>(A, lda, Korig, nslab, wh, wl,
                                                       bias, C, ldc, N, mrs, ss, sq2,
                                                       pmax, srcE, dstE);
}

extern "C" void kernel_launch(void* const* d_in, const int* in_sizes, int n_in,
                              void* d_out, int out_size)
{
    (void)in_sizes; (void)n_in; (void)out_size;
    const float* cell    = (const float*)d_in[0];
    const float* drug_x  = (const float*)d_in[1];
    const int*   eidx    = (const int*)  d_in[2];
    const float* ce1w = (const float*)d_in[4];  const float* ce1b = (const float*)d_in[5];
    const float* ce2w = (const float*)d_in[6];  const float* ce2b = (const float*)d_in[7];
    const float* ce3w = (const float*)d_in[8];  const float* ce3b = (const float*)d_in[9];
    const float* g11w = (const float*)d_in[10]; const float* g11b = (const float*)d_in[11];
    const float* g12w = (const float*)d_in[12]; const float* g12b = (const float*)d_in[13];
    const float* g21w = (const float*)d_in[14]; const float* g21b = (const float*)d_in[15];
    const float* g22w = (const float*)d_in[16]; const float* g22b = (const float*)d_in[17];
    const float* d1w  = (const float*)d_in[18]; const float* d1b  = (const float*)d_in[19];
    const float* d2w  = (const float*)d_in[20]; const float* d2b  = (const float*)d_in[21];
    const float* f1w  = (const float*)d_in[22]; const float* f1b  = (const float*)d_in[23];
    const float* f2w  = (const float*)d_in[24]; const float* f2b  = (const float*)d_in[25];
    const float* f3w  = (const float*)d_in[26]; const float* f3b  = (const float*)d_in[27];

    const int* src = eidx;
    const int* dst = eidx + NEDGES;
    float* out = (float*)d_out;

    float *A, *Bf, *c1, *c2, *z, *p, *q, *f2buf;
    double* stats;
    float2* mrs;
    __nv_bfloat16 *whi, *wlo;
    cudaGetSymbolAddress((void**)&A,     g_A);
    cudaGetSymbolAddress((void**)&Bf,    g_Bf);
    cudaGetSymbolAddress((void**)&c1,    g_c1);
    cudaGetSymbolAddress((void**)&c2,    g_c2);
    cudaGetSymbolAddress((void**)&z,     g_z);
    cudaGetSymbolAddress((void**)&p,     g_p);
    cudaGetSymbolAddress((void**)&q,     g_q);
    cudaGetSymbolAddress((void**)&f2buf, g_f2);
    cudaGetSymbolAddress((void**)&stats, g_stats);
    cudaGetSymbolAddress((void**)&mrs,   g_mrs);
    cudaGetSymbolAddress((void**)&whi,   g_whi);
    cudaGetSymbolAddress((void**)&wlo,   g_wlo);
    double* sum   = stats;
    double* sq    = stats + STATS_N;
    double* g1bs  = stats + 2 * STATS_N;
    double* g1bq  = stats + 2 * STATS_N + G1B_N;

    // ---- prologue: init on NULL; wconv on s2 (overlaps gin1_fused) ----
    init_misc<<<(2 * STATS_N + 2 * G1B_N + 255) / 256, 256>>>(stats, mrs + OFF_F1CAT + 128);
    cudaEventRecord(g_ev1, 0);
    cudaStreamWaitEvent(g_s2, g_ev1, 0);

    wconv_all<<<219, 256, 0, g_s2>>>(ce1w, ce2w, ce3w, g12w, g21w, g22w,
                                     d1w, d2w, f1w, f2w, whi, wlo);
    cudaEventRecord(g_ev3, g_s2);   // weight images ready

    // ---- cell branch continues on s2 ----
    run_tg<0,0,0,0,0>(g_s2, cell, CELLD, CELLD, 29, whi + IMG_CE1, wlo + IMG_CE1, ce1b,
                      c1, 516, 516, nullptr, sum + OFF_CE1, sq + OFF_CE1,
                      nullptr, nullptr, nullptr, BATCH);
    bn_finalize<<<5, 128, 0, g_s2>>>(sum + OFF_CE1, sq + OFF_CE1, mrs + OFF_CE1, 516, BATCH);
    run_tg<1,0,0,0,0>(g_s2, c1, 516, 516, 17, whi + IMG_CE2, wlo + IMG_CE2, ce2b,
                      c2, 256, 256, mrs + OFF_CE1, sum + OFF_CE2, sq + OFF_CE2,
                      nullptr, nullptr, nullptr, BATCH);
    bn_finalize<<<2, 128, 0, g_s2>>>(sum + OFF_CE2, sq + OFF_CE2, mrs + OFF_CE2, 256, BATCH);
    run_tg<1,0,0,0,0>(g_s2, c2, 256, 256, 8, whi + IMG_CE3, wlo + IMG_CE3, ce3b,
                      z, 256, 128, mrs + OFF_CE2, sum + OFF_CE3, sq + OFF_CE3,
                      nullptr, nullptr, nullptr, BATCH);
    bn_finalize<<<1, 128, 0, g_s2>>>(sum + OFF_CE3, sq + OFF_CE3, mrs + OFF_F1CAT, 128, BATCH);
    cudaEventRecord(g_ev2, g_s2);

    // ---- GIN chain (NULL stream); gin1 overlaps wconv ----
    gin1_fused<<<BATCH, 128>>>(drug_x, src, dst, g11w, g11b, A, g1bs, g1bq);
    bn_finalize_g1<<<1, 128>>>(g1bs, g1bq, mrs + OFF_G1A);
    cudaStreamWaitEvent(0, g_ev3, 0);   // need weight images from here on
    run_tg<1,0,1,0,0>(0, A, 128, 128, 4, whi + IMG_G12, wlo + IMG_G12, g12b,
                      Bf, 128, 128, mrs + OFF_G1A, sum + OFF_G1B, sq + OFF_G1B,
                      nullptr, nullptr, nullptr, NNODES);
    bn_finalize<<<1, 128>>>(sum + OFF_G1B, sq + OFF_G1B, mrs + OFF_G1B, 128, NNODES);

    // G21: AGGE — loader relu->BN on raw G12 out; epilogue applies (I+Adj) + bias
    run_tg<3,0,0,0,1>(0, Bf, 128, 128, 4, whi + IMG_G21, wlo + IMG_G21, g21b,
                      A, 128, 128, mrs + OFF_G1B, sum + OFF_G2A, sq + OFF_G2A,
                      nullptr, src, dst, NNODES);
    bn_finalize<<<1, 128>>>(sum + OFF_G2A, sq + OFF_G2A, mrs + OFF_G2A, 128, NNODES);
    // G22: POOL — no C store; per-graph max -> p; stats over relu(h)
    run_tg<1,0,1,1,0>(0, A, 128, 128, 4, whi + IMG_G22, wlo + IMG_G22, g22b,
                      nullptr, 128, 128, mrs + OFF_G2A, sum + OFF_G2B, sq + OFF_G2B,
                      p, nullptr, nullptr, NNODES);
    bn_finalize<<<1, 128>>>(sum + OFF_G2B, sq + OFF_G2B, mrs + OFF_G2B, 128, NNODES);

    // ---- drug head (pooled; D1 applies relu->BN to pmax) ----
    run_tg<3,0,0,0,0>(0, p, 128, 128, 4, whi + IMG_D1, wlo + IMG_D1, d1b,
                      q, 128, 128, mrs + OFF_G2B, sum + OFF_D1, sq + OFF_D1,
                      nullptr, nullptr, nullptr, BATCH);
    bn_finalize<<<1, 128>>>(sum + OFF_D1, sq + OFF_D1, mrs + OFF_D1, 128, BATCH);
    run_tg<1,1,0,0,0>(0, q, 128, 128, 4, whi + IMG_D2, wlo + IMG_D2, d2b,
                      z + 128, 256, 128, mrs + OFF_D1, nullptr, nullptr,
                      nullptr, nullptr, nullptr, BATCH);

    // ---- join: wait for cell branch, then fusion head ----
    cudaStreamWaitEvent(0, g_ev2, 0);
    run_tg<1,0,0,0,0>(0, z, 256, 256, 8, whi + IMG_F1, wlo + IMG_F1, f1b,
                      q, 128, 128, mrs + OFF_F1CAT, sum + OFF_F1, sq + OFF_F1,
                      nullptr, nullptr, nullptr, BATCH);
    bn_finalize<<<1, 128>>>(sum + OFF_F1, sq + OFF_F1, mrs + OFF_F1, 128, BATCH);
    run_tg<2,0,0,0,0>(0, q, 128, 128, 4, whi + IMG_F2, wlo + IMG_F2, f2b,
                      f2buf, 64, 64, mrs + OFF_F1, sum + OFF_F2, sq + OFF_F2,
                      nullptr, nullptr, nullptr, BATCH);
    final_dot<<<(BATCH * 32 + 255) / 256, 256>>>(f2buf, sum + OFF_F2, sq + OFF_F2,
                                                 f3w, f3b, out, BATCH);
}

// round 15
// speedup vs baseline: 1.4463x; 1.4463x over previous
#include <cuda_runtime.h>
#include <cuda_bf16.h>
#include <cstdint>
#include <math.h>

// ---------------------------------------------------------------------------
// Problem constants
// ---------------------------------------------------------------------------
#define BATCH   8192
#define NPG     32
#define EPG     64
#define NNODES  (BATCH * NPG)      // 262144
#define NEDGES  (BATCH * EPG)      // 524288
#define CELLD   908
#define BN_EPS  1e-5f

// BN stats offsets
#define OFF_CE1 0      // 516
#define OFF_CE2 516    // 256
#define OFF_CE3 772    // 128
#define OFF_G1A 900    // 128 (mrs slot only)
#define OFF_G1B 1028   // 128
#define OFF_G2A 1156   // 128
#define OFF_G2B 1284   // 128
#define OFF_D1  1412   // 128
#define OFF_F1  1540   // 128
#define OFF_F2  1668   // 64
#define STATS_N 1732
#define OFF_F1CAT 1732 // mrs-only: 256 entries (ce3 stats | identity)
#define MRS_N   1988
#define G1B_N   (32 * 128)

// Weight slab-image: per (ntile,kslab) block = 128 rows x 40 u16 (pitch 80B) = 10240B
#define IMG_CE1 0
#define IMG_CE2 742400
#define IMG_CE3 916480
#define IMG_G12 957440
#define IMG_G21 977920
#define IMG_G22 998400
#define IMG_D1  1018880
#define IMG_D2  1039360
#define IMG_F1  1059840
#define IMG_F2  1100800
#define IMG_TOTAL 1121280

// ---------------------------------------------------------------------------
// Static device scratch
// ---------------------------------------------------------------------------
__device__ float  g_A [NNODES * 128];
__device__ float  g_Bf[NNODES * 128];
__device__ float  g_c1[BATCH * 516];
__device__ float  g_c2[BATCH * 256];
__device__ float  g_z [BATCH * 256];
__device__ float  g_p [BATCH * 128];
__device__ float  g_q [BATCH * 128];
__device__ float  g_f2[BATCH * 64];
__device__ double g_stats[2 * STATS_N + 2 * G1B_N];
__device__ float2 g_mrs[MRS_N];
__device__ __align__(16) __nv_bfloat16 g_whi[IMG_TOTAL];
__device__ __align__(16) __nv_bfloat16 g_wlo[IMG_TOTAL];

// ---------------------------------------------------------------------------
// Streams/events for fork-join capture (created pre-main; no allocs in launch)
// ---------------------------------------------------------------------------
static cudaStream_t g_s2;
static cudaEvent_t  g_ev1, g_ev2, g_ev3;
static struct StreamInit {
    StreamInit() {
        cudaStreamCreateWithFlags(&g_s2, cudaStreamNonBlocking);
        cudaEventCreateWithFlags(&g_ev1, cudaEventDisableTiming);
        cudaEventCreateWithFlags(&g_ev2, cudaEventDisableTiming);
        cudaEventCreateWithFlags(&g_ev3, cudaEventDisableTiming);
    }
} g_streaminit;

// ---------------------------------------------------------------------------
// PTX helpers
// ---------------------------------------------------------------------------
__device__ __forceinline__ void mma16816(float* c, const uint32_t* a, const uint32_t* b) {
    asm volatile(
        "mma.sync.aligned.m16n8k16.row.col.f32.bf16.bf16.f32 "
        "{%0,%1,%2,%3}, {%4,%5,%6,%7}, {%8,%9}, {%0,%1,%2,%3};"
        : "+f"(c[0]), "+f"(c[1]), "+f"(c[2]), "+f"(c[3])
        : "r"(a[0]), "r"(a[1]), "r"(a[2]), "r"(a[3]), "r"(b[0]), "r"(b[1]));
}

__device__ __forceinline__ void ldsm4(uint32_t* r, uint32_t addr) {
    asm volatile("ldmatrix.sync.aligned.m8n8.x4.shared.b16 {%0,%1,%2,%3}, [%4];"
                 : "=r"(r[0]), "=r"(r[1]), "=r"(r[2]), "=r"(r[3]) : "r"(addr));
}

__device__ __forceinline__ uint32_t s2u(const void* p) {
    uint32_t a;
    asm("{ .reg .u64 t; cvta.to.shared.u64 t, %1; cvt.u32.u64 %0, t; }"
        : "=r"(a) : "l"(p));
    return a;
}

__device__ __forceinline__ void cpasync16(uint32_t dst, const void* src) {
    asm volatile("cp.async.cg.shared.global [%0], [%1], 16;"
                 :: "r"(dst), "l"(src) : "memory");
}
#define CP_COMMIT() asm volatile("cp.async.commit_group;" ::: "memory")
#define CP_WAIT0()  asm volatile("cp.async.wait_group 0;"  ::: "memory")

__device__ __forceinline__ uint32_t packbf(float a, float b) {
    __nv_bfloat16 ha = __float2bfloat16(a), hb = __float2bfloat16(b);
    return (uint32_t)__bfloat16_as_ushort(ha) |
           ((uint32_t)__bfloat16_as_ushort(hb) << 16);
}

// order-preserving float<->uint for atomicMax
__device__ __forceinline__ uint32_t encf(float f) {
    uint32_t b = __float_as_uint(f);
    return (b & 0x80000000u) ? ~b : (b | 0x80000000u);
}
__device__ __forceinline__ float decf(uint32_t u) {
    return (u & 0x80000000u) ? __uint_as_float(u ^ 0x80000000u) : __uint_as_float(~u);
}

__device__ __forceinline__ float2 mrs_of(const double* sum, const double* sq,
                                         int c, float invM) {
    float m = (float)sum[c] * invM;
    float v = (float)sq[c] * invM - m * m;
    return make_float2(m, rsqrtf(v + BN_EPS));
}

// ---------------------------------------------------------------------------
// Fused weight conversion (unchanged)
// ---------------------------------------------------------------------------
__global__ __launch_bounds__(256)
void wconv_all(const float* w0, const float* w1, const float* w2, const float* w3,
               const float* w4, const float* w5, const float* w6, const float* w7,
               const float* w8, const float* w9,
               __nv_bfloat16* __restrict__ hi, __nv_bfloat16* __restrict__ lo)
{
    constexpr int WK[10]   = {908, 516, 256, 128, 128, 128, 128, 128, 256, 128};
    constexpr int WN[10]   = {516, 256, 128, 128, 128, 128, 128, 128, 128, 64};
    constexpr int WNS[10]  = {29, 17, 8, 4, 4, 4, 4, 4, 8, 4};
    constexpr int WCUM[11] = {0, 145, 179, 187, 191, 195, 199, 203, 207, 215, 219};
    constexpr int WIOF[10] = {IMG_CE1, IMG_CE2, IMG_CE3, IMG_G12, IMG_G21,
                              IMG_G22, IMG_D1, IMG_D2, IMG_F1, IMG_F2};

    __shared__ float tile[32][129];

    int blk = blockIdx.x;
    int wi = 0;
    #pragma unroll
    for (int i = 0; i < 10; i++)
        if (blk >= WCUM[i] && blk < WCUM[i + 1]) wi = i;
    int local = blk - WCUM[wi];
    int nslab = WNS[wi];
    int nt = local / nslab, s = local - nt * nslab;
    int K = WK[wi], N = WN[wi];

    const float* W;
    switch (wi) {
        case 0: W = w0; break; case 1: W = w1; break; case 2: W = w2; break;
        case 3: W = w3; break; case 4: W = w4; break; case 5: W = w5; break;
        case 6: W = w6; break; case 7: W = w7; break; case 8: W = w8; break;
        default: W = w9; break;
    }

    int tid = threadIdx.x;
    int nc = tid & 127, kq = tid >> 7;
    #pragma unroll
    for (int i = 0; i < 16; i++) {
        int k = kq + i * 2;
        int gk = s * 32 + k, gn = nt * 128 + nc;
        float v = (gk < K && gn < N) ? W[(size_t)gk * N + gn] : 0.f;
        tile[k][nc] = v;
    }
    __syncthreads();

    char* hb = (char*)(hi + WIOF[wi]) + (size_t)local * 10240;
    char* lb = (char*)(lo + WIOF[wi]) + (size_t)local * 10240;
    #pragma unroll
    for (int it = 0; it < 2; it++) {
        int idx = tid + it * 256;
        int n = idx >> 2, q = idx & 3;
        uint32_t h[4], l[4];
        #pragma unroll
        for (int j = 0; j < 4; j++) {
            float f0 = tile[q * 8 + 2 * j][n];
            float f1 = tile[q * 8 + 2 * j + 1][n];
            float h0 = __bfloat162float(__float2bfloat16(f0));
            float h1 = __bfloat162float(__float2bfloat16(f1));
            h[j] = packbf(f0, f1);
            l[j] = packbf(f0 - h0, f1 - h1);
        }
        *(uint4*)(hb + n * 80 + q * 16) = make_uint4(h[0], h[1], h[2], h[3]);
        *(uint4*)(lb + n * 80 + q * 16) = make_uint4(l[0], l[1], l[2], l[3]);
    }
}

// ---------------------------------------------------------------------------
// Templated fused tensor-core GEMM (mma.sync bf16 split-3, fp32 accum):
//   C = EPI_ACT( IN_ACT(BN_lut(A)) @ W + bias )
//   STAT_PRE: stats over relu(C);  POOL: per-graph max -> pmax, no C store
//   AGGE: GIN aggregation fused into EPILOGUE via (I+Adj)(yW) = ((I+Adj)y)W
// IN_ACT: 0 none, 1 BN->relu, 2 BN->elu, 3 relu->BN
// ---------------------------------------------------------------------------
#define TG_SMEM 81920

template<int IN_ACT, int EPI_ACT, int STAT_PRE, int POOL, int AGGE>
__global__ __launch_bounds__(256, 2)
void tgemm(const float* __restrict__ A, int lda, int Korig, int nslab,
           const __nv_bfloat16* __restrict__ Whi, const __nv_bfloat16* __restrict__ Wlo,
           const float* __restrict__ bias,
           float* __restrict__ C, int ldc, int N,
           const float2* __restrict__ mrsIn,
           double* __restrict__ stSum, double* __restrict__ stSq,
           float* __restrict__ pmax,
           const int* __restrict__ srcE, const int* __restrict__ dstE)
{
    extern __shared__ char dynsm[];
    __shared__ float ssum[128], ssq[128];
    __shared__ uint32_t pmS[POOL ? 512 : 1];
    __shared__ int lsE[AGGE ? 256 : 1], ldE[AGGE ? 256 : 1];

    const int tid = threadIdx.x;
    const int wid = tid >> 5, lane = tid & 31;
    const int mt = blockIdx.y, ntile = blockIdx.x;
    const int bn0 = ntile * 128;

    const float* Ab = A + (size_t)mt * 128 * lda;
    const char* BHall = (const char*)Whi + (size_t)ntile * nslab * 10240;
    const char* BLall = (const char*)Wlo + (size_t)ntile * nslab * 10240;

    const uint32_t smu = s2u(dynsm);
    const int wm = (wid >> 2) * 64, wn = (wid & 3) * 32;

    if (AGGE) {
        lsE[tid] = srcE[mt * 256 + tid] & (NPG - 1);
        ldE[tid] = dstE[mt * 256 + tid] & (NPG - 1);
    }

    float acc[4][4][4];
    #pragma unroll
    for (int a = 0; a < 4; a++)
        #pragma unroll
        for (int b = 0; b < 4; b++)
            #pragma unroll
            for (int c = 0; c < 4; c++) acc[a][b][c] = 0.f;

    float4 av[4];

    auto bload = [&](int s) {
        uint32_t st = (uint32_t)(s & 1) * 10240u;
        uint32_t dh = smu + 40960 + st, dl = smu + 61440 + st;
        const char* sh = BHall + (size_t)s * 10240;
        const char* sl = BLall + (size_t)s * 10240;
        #pragma unroll
        for (int i = tid; i < 640; i += 256) {
            cpasync16(dh + i * 16, sh + i * 16);
            cpasync16(dl + i * 16, sl + i * 16);
        }
        CP_COMMIT();
    };

    auto gload = [&](int s) {
        int k0 = s * 32;
        #pragma unroll
        for (int j = 0; j < 4; j++) {
            int f = tid + 256 * j;
            int r = f >> 3, c4 = f & 7;
            int kc = k0 + c4 * 4;
            const float* ap = Ab + (size_t)r * lda + kc;
            if (kc + 3 < Korig) {
                av[j] = *(const float4*)ap;
            } else {
                av[j].x = (kc + 0 < Korig) ? ap[0] : 0.f;
                av[j].y = (kc + 1 < Korig) ? ap[1] : 0.f;
                av[j].z = (kc + 2 < Korig) ? ap[2] : 0.f;
                av[j].w = (kc + 3 < Korig) ? ap[3] : 0.f;
            }
        }
    };

    auto convstore = [&](int s) {
        uint32_t st = (uint32_t)(s & 1) * 10240u;
        char* AH = dynsm + st;
        char* AL = dynsm + 20480 + st;
        int k0 = s * 32;
        #pragma unroll
        for (int j = 0; j < 4; j++) {
            int f = tid + 256 * j;
            int r = f >> 3, c4 = f & 7;
            float4 v = av[j];
            if (IN_ACT != 0) {
                int kc = k0 + c4 * 4;
                float2 p0 = mrsIn[kc + 0], p1 = mrsIn[kc + 1];
                float2 p2 = mrsIn[kc + 2], p3 = mrsIn[kc + 3];
                if (IN_ACT == 3) {
                    v.x = (fmaxf(v.x, 0.f) - p0.x) * p0.y;
                    v.y = (fmaxf(v.y, 0.f) - p1.x) * p1.y;
                    v.z = (fmaxf(v.z, 0.f) - p2.x) * p2.y;
                    v.w = (fmaxf(v.w, 0.f) - p3.x) * p3.y;
                } else {
                    v.x = (v.x - p0.x) * p0.y;
                    v.y = (v.y - p1.x) * p1.y;
                    v.z = (v.z - p2.x) * p2.y;
                    v.w = (v.w - p3.x) * p3.y;
                    if (IN_ACT == 1) {
                        v.x = fmaxf(v.x, 0.f); v.y = fmaxf(v.y, 0.f);
                        v.z = fmaxf(v.z, 0.f); v.w = fmaxf(v.w, 0.f);
                    } else if (IN_ACT == 2) {
                        v.x = (v.x > 0.f) ? v.x : expm1f(v.x);
                        v.y = (v.y > 0.f) ? v.y : expm1f(v.y);
                        v.z = (v.z > 0.f) ? v.z : expm1f(v.z);
                        v.w = (v.w > 0.f) ? v.w : expm1f(v.w);
                    }
                }
            }
            float hx = __bfloat162float(__float2bfloat16(v.x));
            float hy = __bfloat162float(__float2bfloat16(v.y));
            float hz = __bfloat162float(__float2bfloat16(v.z));
            float hw = __bfloat162float(__float2bfloat16(v.w));
            uint2 h2, l2;
            h2.x = packbf(v.x, v.y);  h2.y = packbf(v.z, v.w);
            l2.x = packbf(v.x - hx, v.y - hy);
            l2.y = packbf(v.z - hz, v.w - hw);
            uint32_t off = (uint32_t)(r * 80 + c4 * 8);
            *(uint2*)(AH + off) = h2;
            *(uint2*)(AL + off) = l2;
        }
    };

    auto mma_slab = [&](int s) {
        uint32_t st = (uint32_t)(s & 1) * 10240u;
        uint32_t AHb = smu + st, ALb = smu + 20480 + st;
        uint32_t BHb = smu + 40960 + st, BLb = smu + 61440 + st;
        #pragma unroll
        for (int kk = 0; kk < 2; kk++) {
            uint32_t bh[4][2], bl[4][2];
            #pragma unroll
            for (int ni2 = 0; ni2 < 2; ni2++) {
                int n0 = wn + ni2 * 16 + ((lane >> 4) << 3) + (lane & 7);
                uint32_t off = (uint32_t)(n0 * 40 + kk * 16 + ((lane >> 3) & 1) * 8) * 2;
                uint32_t t4[4];
                ldsm4(t4, BHb + off);
                bh[2 * ni2][0] = t4[0]; bh[2 * ni2][1] = t4[1];
                bh[2 * ni2 + 1][0] = t4[2]; bh[2 * ni2 + 1][1] = t4[3];
                ldsm4(t4, BLb + off);
                bl[2 * ni2][0] = t4[0]; bl[2 * ni2][1] = t4[1];
                bl[2 * ni2 + 1][0] = t4[2]; bl[2 * ni2 + 1][1] = t4[3];
            }
            #pragma unroll
            for (int mi = 0; mi < 4; mi++) {
                int row = wm + mi * 16 + (lane & 15);
                uint32_t off = (uint32_t)(row * 40 + kk * 16 + (lane >> 4) * 8) * 2;
                uint32_t ah[4], al[4];
                ldsm4(ah, AHb + off);
                ldsm4(al, ALb + off);
                #pragma unroll
                for (int ni = 0; ni < 4; ni++) {
                    mma16816(acc[mi][ni], ah, bh[ni]);
                    mma16816(acc[mi][ni], ah, bl[ni]);
                    mma16816(acc[mi][ni], al, bh[ni]);
                }
            }
        }
    };

    // ---- pipelined mainloop ----
    bload(0);
    gload(0);
    convstore(0);
    CP_WAIT0();
    __syncthreads();
    for (int s = 0; s < nslab; s++) {
        bool more = (s + 1 < nslab);
        if (more) { bload(s + 1); gload(s + 1); }
        mma_slab(s);
        if (more) { convstore(s + 1); CP_WAIT0(); }
        __syncthreads();
    }

    // ---- epilogue ----
    bool hasStats = (stSum != nullptr);
    if (hasStats && tid < 128) { ssum[tid] = 0.f; ssq[tid] = 0.f; }
    if (POOL) { pmS[tid] = 0u; pmS[tid + 256] = 0u; }
    __syncthreads();

    if (AGGE) {
        // out = u + Adj.u + bias, u = raw GEMM result; 2 phases of 64 rows
        float* u2 = (float*)dynsm;              // 64 x 129 floats
        float* ag = (float*)(dynsm + 33024);    // 64 x 129 floats
        const int gph = tid >> 7;               // graph within phase (0/1)
        const int cc  = tid & 127;
        const float bv = bias[cc];
        #pragma unroll
        for (int ph = 0; ph < 2; ph++) {
            if ((wid >> 2) == ph) {
                #pragma unroll
                for (int ni = 0; ni < 4; ni++) {
                    int lc0 = wn + ni * 8 + 2 * (lane & 3);
                    #pragma unroll
                    for (int mi = 0; mi < 4; mi++) {
                        int lr = mi * 16 + (lane >> 2);
                        u2[lr * 129 + lc0]           = acc[mi][ni][0];
                        u2[lr * 129 + lc0 + 1]       = acc[mi][ni][1];
                        u2[(lr + 8) * 129 + lc0]     = acc[mi][ni][2];
                        u2[(lr + 8) * 129 + lc0 + 1] = acc[mi][ni][3];
                    }
                }
            }
            __syncthreads();
            int rb = gph * 32;
            #pragma unroll 4
            for (int r = 0; r < 32; r++) ag[(rb + r) * 129 + cc] = 0.f;
            int eb = (ph * 2 + gph) * 64;
            for (int e = 0; e < 64; e++)
                ag[(rb + ldE[eb + e]) * 129 + cc] += u2[(rb + lsE[eb + e]) * 129 + cc];
            float s1 = 0.f, s2 = 0.f;
            #pragma unroll 4
            for (int r = 0; r < 32; r++) {
                float o = u2[(rb + r) * 129 + cc] + ag[(rb + r) * 129 + cc] + bv;
                C[(size_t)(mt * 128 + ph * 64 + rb + r) * ldc + cc] = o;
                s1 += o; s2 += o * o;
            }
            atomicAdd(&ssum[cc], s1);
            atomicAdd(&ssq[cc], s2);
            __syncthreads();
        }
    } else {
        #pragma unroll
        for (int ni = 0; ni < 4; ni++) {
            float ps0 = 0.f, ps1 = 0.f, pq0 = 0.f, pq1 = 0.f;
            int lc0 = wn + ni * 8 + 2 * (lane & 3);
            int gc0 = bn0 + lc0;
            float b0v = (gc0 < N) ? bias[gc0] : 0.f;
            float b1v = (gc0 + 1 < N) ? bias[gc0 + 1] : 0.f;
            #pragma unroll
            for (int mi = 0; mi < 4; mi++) {
                float v00 = acc[mi][ni][0] + b0v, v01 = acc[mi][ni][1] + b1v;
                float v10 = acc[mi][ni][2] + b0v, v11 = acc[mi][ni][3] + b1v;
                int lr0 = wm + mi * 16 + (lane >> 2);
                if (hasStats) {
                    float s00 = STAT_PRE ? fmaxf(v00, 0.f) : v00;
                    float s01 = STAT_PRE ? fmaxf(v01, 0.f) : v01;
                    float s10 = STAT_PRE ? fmaxf(v10, 0.f) : v10;
                    float s11 = STAT_PRE ? fmaxf(v11, 0.f) : v11;
                    ps0 += s00 + s10;  ps1 += s01 + s11;
                    pq0 += s00 * s00 + s10 * s10;
                    pq1 += s01 * s01 + s11 * s11;
                }
                if (POOL) {
                    atomicMax(&pmS[(lr0 >> 5) * 128 + lc0],           encf(v00));
                    atomicMax(&pmS[(lr0 >> 5) * 128 + lc0 + 1],       encf(v01));
                    atomicMax(&pmS[((lr0 + 8) >> 5) * 128 + lc0],     encf(v10));
                    atomicMax(&pmS[((lr0 + 8) >> 5) * 128 + lc0 + 1], encf(v11));
                } else if (gc0 < N) {
                    float o00 = v00, o01 = v01, o10 = v10, o11 = v11;
                    if (EPI_ACT == 1) {
                        o00 = fmaxf(o00, 0.f); o01 = fmaxf(o01, 0.f);
                        o10 = fmaxf(o10, 0.f); o11 = fmaxf(o11, 0.f);
                    }
                    int r0 = mt * 128 + lr0;
                    *(float2*)&C[(size_t)r0 * ldc + gc0]       = make_float2(o00, o01);
                    *(float2*)&C[(size_t)(r0 + 8) * ldc + gc0] = make_float2(o10, o11);
                }
            }
            if (hasStats) {
                #pragma unroll
                for (int off = 16; off >= 4; off >>= 1) {
                    ps0 += __shfl_xor_sync(0xffffffffu, ps0, off);
                    ps1 += __shfl_xor_sync(0xffffffffu, ps1, off);
                    pq0 += __shfl_xor_sync(0xffffffffu, pq0, off);
                    pq1 += __shfl_xor_sync(0xffffffffu, pq1, off);
                }
                if (lane < 4) {
                    int lc = wn + ni * 8 + 2 * lane;
                    atomicAdd(&ssum[lc], ps0);     atomicAdd(&ssq[lc], pq0);
                    atomicAdd(&ssum[lc + 1], ps1); atomicAdd(&ssq[lc + 1], pq1);
                }
            }
        }
    }
    __syncthreads();
    if (hasStats && tid < 128 && bn0 + tid < N) {
        atomicAdd(&stSum[bn0 + tid], (double)ssum[tid]);
        atomicAdd(&stSq[bn0 + tid],  (double)ssq[tid]);
    }
    if (POOL) {
        #pragma unroll
        for (int i = tid; i < 512; i += 256) {
            int g = mt * 4 + (i >> 7);
            pmax[(size_t)g * 128 + (i & 127)] = decf(pmS[i]);
        }
    }
}

// ---------------------------------------------------------------------------
// BN helper kernels
// ---------------------------------------------------------------------------
__global__ void init_misc(double* stats, float2* ident) {
    int i = blockIdx.x * blockDim.x + threadIdx.x;
    if (i < 2 * STATS_N + 2 * G1B_N) stats[i] = 0.0;
    if (i < 128) ident[i] = make_float2(0.f, 1.f);
}

__global__ void bn_finalize(const double* __restrict__ sum, const double* __restrict__ sumsq,
                            float2* __restrict__ mrs, int C, int M)
{
    int c = blockIdx.x * blockDim.x + threadIdx.x;
    if (c >= C) return;
    double m = sum[c] / (double)M;
    double v = sumsq[c] / (double)M - m * m;
    mrs[c] = make_float2((float)m, rsqrtf((float)v + BN_EPS));
}

__global__ void bn_finalize_g1(const double* __restrict__ bsum,
                               const double* __restrict__ bsq,
                               float2* __restrict__ mrs)
{
    int c = threadIdx.x;
    double s = 0.0, q = 0.0;
    #pragma unroll
    for (int b = 0; b < 32; b++) {
        s += bsum[b * 128 + c];
        q += bsq[b * 128 + c];
    }
    double m = s / (double)NNODES;
    double v = q / (double)NNODES - m * m;
    mrs[c] = make_float2((float)m, rsqrtf((float)v + BN_EPS));
}

// ---------------------------------------------------------------------------
// Graph kernels
// ---------------------------------------------------------------------------
// gin1 + bucketed stats; parallel edge aggregation via smem atomics
__global__ void gin1_fused(const float* __restrict__ X,
                           const int* __restrict__ src, const int* __restrict__ dst,
                           const float* __restrict__ W, const float* __restrict__ b,
                           float* __restrict__ out,
                           double* __restrict__ bsum, double* __restrict__ bsq)
{
    __shared__ float xs[NPG][9];
    __shared__ float h0[NPG][9];
    __shared__ float Ws[9][128];
    __shared__ float bsh[128];
    __shared__ int   ls[EPG], ld[EPG];
    int g = blockIdx.x;
    int t = threadIdx.x;
    for (int i = t; i < NPG * 9; i += 128) {
        xs[i / 9][i % 9] = X[(size_t)g * NPG * 9 + i];
        h0[i / 9][i % 9] = 0.f;
    }
    if (t < EPG) {
        ls[t] = src[g * EPG + t] & (NPG - 1);
        ld[t] = dst[g * EPG + t] & (NPG - 1);
    }
    for (int i = t; i < 9 * 128; i += 128) Ws[i / 128][i % 128] = W[i];
    bsh[t] = b[t];
    __syncthreads();
    // parallel edge aggregation: 576 (edge, feature) items over 128 threads
    for (int i = t; i < EPG * 9; i += 128) {
        int e = i / 9, c = i - e * 9;
        atomicAdd(&h0[ld[e]][c], xs[ls[e]][c]);
    }
    __syncthreads();
    for (int i = t; i < NPG * 9; i += 128) h0[i / 9][i % 9] += xs[i / 9][i % 9];
    __syncthreads();
    float s1 = 0.f, s2 = 0.f;
    for (int r = 0; r < NPG; r++) {
        float acc = bsh[t];
        #pragma unroll
        for (int k = 0; k < 9; k++) acc += h0[r][k] * Ws[k][t];
        out[((size_t)g * NPG + r) * 128 + t] = acc;
        s1 += acc; s2 += acc * acc;
    }
    int bkt = (g & 31) * 128 + t;
    atomicAdd(&bsum[bkt], (double)s1);
    atomicAdd(&bsq[bkt],  (double)s2);
}

// y[i] = dot(elu(BN(Z[i,:])), w) + b; BN finalize inline from sums
__global__ void final_dot(const float* __restrict__ Z,
                          const double* __restrict__ sum, const double* __restrict__ sq,
                          const float* __restrict__ w, const float* __restrict__ b,
                          float* __restrict__ y, int Bn)
{
    int warp = (blockIdx.x * blockDim.x + threadIdx.x) >> 5;
    int lane = threadIdx.x & 31;
    if (warp >= Bn) return;
    float invM = 1.f / (float)BATCH;
    float2 p0 = mrs_of(sum, sq, lane, invM);
    float2 p1 = mrs_of(sum, sq, 32 + lane, invM);
    float x0 = (Z[(size_t)warp * 64 + lane]      - p0.x) * p0.y;
    float x1 = (Z[(size_t)warp * 64 + 32 + lane] - p1.x) * p1.y;
    x0 = (x0 > 0.f) ? x0 : expm1f(x0);
    x1 = (x1 > 0.f) ? x1 : expm1f(x1);
    float s = x0 * w[lane] + x1 * w[32 + lane];
    #pragma unroll
    for (int o = 16; o; o >>= 1) s += __shfl_down_sync(0xffffffffu, s, o);
    if (lane == 0) y[warp] = s + b[0];
}

// ---------------------------------------------------------------------------
// Host side
// ---------------------------------------------------------------------------
template<int IA, int EA, int SP, int PL, int AG>
static inline void run_tg(cudaStream_t st, const float* A, int lda, int Korig, int nslab,
                          const __nv_bfloat16* wh, const __nv_bfloat16* wl,
                          const float* bias, float* C, int ldc, int N,
                          const float2* mrs, double* ss, double* sq2,
                          float* pmax, const int* srcE, const int* dstE, int M)
{
    cudaFuncSetAttribute(tgemm<IA, EA, SP, PL, AG>,
                         cudaFuncAttributeMaxDynamicSharedMemorySize, TG_SMEM);
    dim3 g((N + 127) / 128, M / 128);
    tgemm<IA, EA, SP, PL, AG><<<g, 256, TG_SMEM, st>>>(A, lda, Korig, nslab, wh, wl,
                                                       bias, C, ldc, N, mrs, ss, sq2,
                                                       pmax, srcE, dstE);
}

extern "C" void kernel_launch(void* const* d_in, const int* in_sizes, int n_in,
                              void* d_out, int out_size)
{
    (void)in_sizes; (void)n_in; (void)out_size;
    const float* cell    = (const float*)d_in[0];
    const float* drug_x  = (const float*)d_in[1];
    const int*   eidx    = (const int*)  d_in[2];
    const float* ce1w = (const float*)d_in[4];  const float* ce1b = (const float*)d_in[5];
    const float* ce2w = (const float*)d_in[6];  const float* ce2b = (const float*)d_in[7];
    const float* ce3w = (const float*)d_in[8];  const float* ce3b = (const float*)d_in[9];
    const float* g11w = (const float*)d_in[10]; const float* g11b = (const float*)d_in[11];
    const float* g12w = (const float*)d_in[12]; const float* g12b = (const float*)d_in[13];
    const float* g21w = (const float*)d_in[14]; const float* g21b = (const float*)d_in[15];
    const float* g22w = (const float*)d_in[16]; const float* g22b = (const float*)d_in[17];
    const float* d1w  = (const float*)d_in[18]; const float* d1b  = (const float*)d_in[19];
    const float* d2w  = (const float*)d_in[20]; const float* d2b  = (const float*)d_in[21];
    const float* f1w  = (const float*)d_in[22]; const float* f1b  = (const float*)d_in[23];
    const float* f2w  = (const float*)d_in[24]; const float* f2b  = (const float*)d_in[25];
    const float* f3w  = (const float*)d_in[26]; const float* f3b  = (const float*)d_in[27];

    const int* src = eidx;
    const int* dst = eidx + NEDGES;
    float* out = (float*)d_out;

    float *A, *Bf, *c1, *c2, *z, *p, *q, *f2buf;
    double* stats;
    float2* mrs;
    __nv_bfloat16 *whi, *wlo;
    cudaGetSymbolAddress((void**)&A,     g_A);
    cudaGetSymbolAddress((void**)&Bf,    g_Bf);
    cudaGetSymbolAddress((void**)&c1,    g_c1);
    cudaGetSymbolAddress((void**)&c2,    g_c2);
    cudaGetSymbolAddress((void**)&z,     g_z);
    cudaGetSymbolAddress((void**)&p,     g_p);
    cudaGetSymbolAddress((void**)&q,     g_q);
    cudaGetSymbolAddress((void**)&f2buf, g_f2);
    cudaGetSymbolAddress((void**)&stats, g_stats);
    cudaGetSymbolAddress((void**)&mrs,   g_mrs);
    cudaGetSymbolAddress((void**)&whi,   g_whi);
    cudaGetSymbolAddress((void**)&wlo,   g_wlo);
    double* sum   = stats;
    double* sq    = stats + STATS_N;
    double* g1bs  = stats + 2 * STATS_N;
    double* g1bq  = stats + 2 * STATS_N + G1B_N;

    // ---- prologue: init on NULL; wconv on s2 (overlaps gin1_fused) ----
    init_misc<<<(2 * STATS_N + 2 * G1B_N + 255) / 256, 256>>>(stats, mrs + OFF_F1CAT + 128);
    cudaEventRecord(g_ev1, 0);
    cudaStreamWaitEvent(g_s2, g_ev1, 0);

    wconv_all<<<219, 256, 0, g_s2>>>(ce1w, ce2w, ce3w, g12w, g21w, g22w,
                                     d1w, d2w, f1w, f2w, whi, wlo);
    cudaEventRecord(g_ev3, g_s2);   // weight images ready

    // ---- cell branch continues on s2 ----
    run_tg<0,0,0,0,0>(g_s2, cell, CELLD, CELLD, 29, whi + IMG_CE1, wlo + IMG_CE1, ce1b,
                      c1, 516, 516, nullptr, sum + OFF_CE1, sq + OFF_CE1,
                      nullptr, nullptr, nullptr, BATCH);
    bn_finalize<<<5, 128, 0, g_s2>>>(sum + OFF_CE1, sq + OFF_CE1, mrs + OFF_CE1, 516, BATCH);
    run_tg<1,0,0,0,0>(g_s2, c1, 516, 516, 17, whi + IMG_CE2, wlo + IMG_CE2, ce2b,
                      c2, 256, 256, mrs + OFF_CE1, sum + OFF_CE2, sq + OFF_CE2,
                      nullptr, nullptr, nullptr, BATCH);
    bn_finalize<<<2, 128, 0, g_s2>>>(sum + OFF_CE2, sq + OFF_CE2, mrs + OFF_CE2, 256, BATCH);
    run_tg<1,0,0,0,0>(g_s2, c2, 256, 256, 8, whi + IMG_CE3, wlo + IMG_CE3, ce3b,
                      z, 256, 128, mrs + OFF_CE2, sum + OFF_CE3, sq + OFF_CE3,
                      nullptr, nullptr, nullptr, BATCH);
    bn_finalize<<<1, 128, 0, g_s2>>>(sum + OFF_CE3, sq + OFF_CE3, mrs + OFF_F1CAT, 128, BATCH);
    cudaEventRecord(g_ev2, g_s2);

    // ---- GIN chain (NULL stream); gin1 overlaps wconv ----
    gin1_fused<<<BATCH, 128>>>(drug_x, src, dst, g11w, g11b, A, g1bs, g1bq);
    bn_finalize_g1<<<1, 128>>>(g1bs, g1bq, mrs + OFF_G1A);
    cudaStreamWaitEvent(0, g_ev3, 0);   // need weight images from here on
    run_tg<1,0,1,0,0>(0, A, 128, 128, 4, whi + IMG_G12, wlo + IMG_G12, g12b,
                      Bf, 128, 128, mrs + OFF_G1A, sum + OFF_G1B, sq + OFF_G1B,
                      nullptr, nullptr, nullptr, NNODES);
    bn_finalize<<<1, 128>>>(sum + OFF_G1B, sq + OFF_G1B, mrs + OFF_G1B, 128, NNODES);

    // G21: AGGE — loader relu->BN on raw G12 out; epilogue applies (I+Adj) + bias
    run_tg<3,0,0,0,1>(0, Bf, 128, 128, 4, whi + IMG_G21, wlo + IMG_G21, g21b,
                      A, 128, 128, mrs + OFF_G1B, sum + OFF_G2A, sq + OFF_G2A,
                      nullptr, src, dst, NNODES);
    bn_finalize<<<1, 128>>>(sum + OFF_G2A, sq + OFF_G2A, mrs + OFF_G2A, 128, NNODES);
    // G22: POOL — no C store; per-graph max -> p; stats over relu(h)
    run_tg<1,0,1,1,0>(0, A, 128, 128, 4, whi + IMG_G22, wlo + IMG_G22, g22b,
                      nullptr, 128, 128, mrs + OFF_G2A, sum + OFF_G2B, sq + OFF_G2B,
                      p, nullptr, nullptr, NNODES);
    bn_finalize<<<1, 128>>>(sum + OFF_G2B, sq + OFF_G2B, mrs + OFF_G2B, 128, NNODES);

    // ---- drug head (pooled; D1 applies relu->BN to pmax) ----
    run_tg<3,0,0,0,0>(0, p, 128, 128, 4, whi + IMG_D1, wlo + IMG_D1, d1b,
                      q, 128, 128, mrs + OFF_G2B, sum + OFF_D1, sq + OFF_D1,
                      nullptr, nullptr, nullptr, BATCH);
    bn_finalize<<<1, 128>>>(sum + OFF_D1, sq + OFF_D1, mrs + OFF_D1, 128, BATCH);
    run_tg<1,1,0,0,0>(0, q, 128, 128, 4, whi + IMG_D2, wlo + IMG_D2, d2b,
                      z + 128, 256, 128, mrs + OFF_D1, nullptr, nullptr,
                      nullptr, nullptr, nullptr, BATCH);

    // ---- join: wait for cell branch, then fusion head ----
    cudaStreamWaitEvent(0, g_ev2, 0);
    run_tg<1,0,0,0,0>(0, z, 256, 256, 8, whi + IMG_F1, wlo + IMG_F1, f1b,
                      q, 128, 128, mrs + OFF_F1CAT, sum + OFF_F1, sq + OFF_F1,
                      nullptr, nullptr, nullptr, BATCH);
    bn_finalize<<<1, 128>>>(sum + OFF_F1, sq + OFF_F1, mrs + OFF_F1, 128, BATCH);
    run_tg<2,0,0,0,0>(0, q, 128, 128, 4, whi + IMG_F2, wlo + IMG_F2, f2b,
                      f2buf, 64, 64, mrs + OFF_F1, sum + OFF_F2, sq + OFF_F2,
                      nullptr, nullptr, nullptr, BATCH);
    final_dot<<<(BATCH * 32 + 255) / 256, 256>>>(f2buf, sum + OFF_F2, sq + OFF_F2,
                                                 f3w, f3b, out, BATCH);
}

// round 16
// speedup vs baseline: 1.4598x; 1.0093x over previous
#include <cuda_runtime.h>
#include <cuda_bf16.h>
#include <cstdint>
#include <math.h>

// ---------------------------------------------------------------------------
// Problem constants
// ---------------------------------------------------------------------------
#define BATCH   8192
#define NPG     32
#define EPG     64
#define NNODES  (BATCH * NPG)      // 262144
#define NEDGES  (BATCH * EPG)      // 524288
#define CELLD   908
#define BN_EPS  1e-5f

// BN stats offsets
#define OFF_CE1 0      // 516
#define OFF_CE2 516    // 256
#define OFF_CE3 772    // 128
#define OFF_G1A 900    // 128 (mrs slot only)
#define OFF_G1B 1028   // 128
#define OFF_G2A 1156   // 128
#define OFF_G2B 1284   // 128
#define OFF_D1  1412   // 128
#define OFF_F1  1540   // 128
#define OFF_F2  1668   // 64
#define STATS_N 1732
#define OFF_F1CAT 1732 // mrs-only: 256 entries (ce3 stats | identity)
#define MRS_N   1988
#define G1B_N   (32 * 128)

// Weight slab-image: per (ntile,kslab) block = 128 rows x 40 u16 (pitch 80B) = 10240B
#define IMG_CE1 0
#define IMG_CE2 742400
#define IMG_CE3 916480
#define IMG_G12 957440
#define IMG_G21 977920
#define IMG_G22 998400
#define IMG_D1  1018880
#define IMG_D2  1039360
#define IMG_F1  1059840
#define IMG_F2  1100800
#define IMG_TOTAL 1121280

// ---------------------------------------------------------------------------
// Static device scratch
// ---------------------------------------------------------------------------
__device__ float  g_A [NNODES * 128];
__device__ float  g_Bf[NNODES * 128];
__device__ float  g_c1[BATCH * 516];
__device__ float  g_c2[BATCH * 256];
__device__ float  g_z [BATCH * 256];
__device__ float  g_p [BATCH * 128];
__device__ float  g_q [BATCH * 128];
__device__ float  g_f2[BATCH * 64];
__device__ double g_stats[2 * STATS_N + 2 * G1B_N];
__device__ float2 g_mrs[MRS_N];
__device__ __align__(16) __nv_bfloat16 g_whi[IMG_TOTAL];
__device__ __align__(16) __nv_bfloat16 g_wlo[IMG_TOTAL];

// ---------------------------------------------------------------------------
// Streams/events for fork-join capture (created pre-main; no allocs in launch)
// ---------------------------------------------------------------------------
static cudaStream_t g_s2;
static cudaEvent_t  g_ev1, g_ev2, g_ev3;
static struct StreamInit {
    StreamInit() {
        cudaStreamCreateWithFlags(&g_s2, cudaStreamNonBlocking);
        cudaEventCreateWithFlags(&g_ev1, cudaEventDisableTiming);
        cudaEventCreateWithFlags(&g_ev2, cudaEventDisableTiming);
        cudaEventCreateWithFlags(&g_ev3, cudaEventDisableTiming);
    }
} g_streaminit;

// ---------------------------------------------------------------------------
// PTX helpers
// ---------------------------------------------------------------------------
__device__ __forceinline__ void mma16816(float* c, const uint32_t* a, const uint32_t* b) {
    asm volatile(
        "mma.sync.aligned.m16n8k16.row.col.f32.bf16.bf16.f32 "
        "{%0,%1,%2,%3}, {%4,%5,%6,%7}, {%8,%9}, {%0,%1,%2,%3};"
        : "+f"(c[0]), "+f"(c[1]), "+f"(c[2]), "+f"(c[3])
        : "r"(a[0]), "r"(a[1]), "r"(a[2]), "r"(a[3]), "r"(b[0]), "r"(b[1]));
}

__device__ __forceinline__ void ldsm4(uint32_t* r, uint32_t addr) {
    asm volatile("ldmatrix.sync.aligned.m8n8.x4.shared.b16 {%0,%1,%2,%3}, [%4];"
                 : "=r"(r[0]), "=r"(r[1]), "=r"(r[2]), "=r"(r[3]) : "r"(addr));
}

__device__ __forceinline__ uint32_t s2u(const void* p) {
    uint32_t a;
    asm("{ .reg .u64 t; cvta.to.shared.u64 t, %1; cvt.u32.u64 %0, t; }"
        : "=r"(a) : "l"(p));
    return a;
}

__device__ __forceinline__ void cpasync16(uint32_t dst, const void* src) {
    asm volatile("cp.async.cg.shared.global [%0], [%1], 16;"
                 :: "r"(dst), "l"(src) : "memory");
}
#define CP_COMMIT() asm volatile("cp.async.commit_group;" ::: "memory")
#define CP_WAIT0()  asm volatile("cp.async.wait_group 0;"  ::: "memory")

__device__ __forceinline__ uint32_t packbf(float a, float b) {
    __nv_bfloat16 ha = __float2bfloat16(a), hb = __float2bfloat16(b);
    return (uint32_t)__bfloat16_as_ushort(ha) |
           ((uint32_t)__bfloat16_as_ushort(hb) << 16);
}

// order-preserving float<->uint for atomicMax
__device__ __forceinline__ uint32_t encf(float f) {
    uint32_t b = __float_as_uint(f);
    return (b & 0x80000000u) ? ~b : (b | 0x80000000u);
}
__device__ __forceinline__ float decf(uint32_t u) {
    return (u & 0x80000000u) ? __uint_as_float(u ^ 0x80000000u) : __uint_as_float(~u);
}

__device__ __forceinline__ float2 mrs_of(const double* sum, const double* sq,
                                         int c, float invM) {
    float m = (float)sum[c] * invM;
    float v = (float)sq[c] * invM - m * m;
    return make_float2(m, rsqrtf(v + BN_EPS));
}

// ---------------------------------------------------------------------------
// Fused weight conversion (unchanged)
// ---------------------------------------------------------------------------
__global__ __launch_bounds__(256)
void wconv_all(const float* w0, const float* w1, const float* w2, const float* w3,
               const float* w4, const float* w5, const float* w6, const float* w7,
               const float* w8, const float* w9,
               __nv_bfloat16* __restrict__ hi, __nv_bfloat16* __restrict__ lo)
{
    constexpr int WK[10]   = {908, 516, 256, 128, 128, 128, 128, 128, 256, 128};
    constexpr int WN[10]   = {516, 256, 128, 128, 128, 128, 128, 128, 128, 64};
    constexpr int WNS[10]  = {29, 17, 8, 4, 4, 4, 4, 4, 8, 4};
    constexpr int WCUM[11] = {0, 145, 179, 187, 191, 195, 199, 203, 207, 215, 219};
    constexpr int WIOF[10] = {IMG_CE1, IMG_CE2, IMG_CE3, IMG_G12, IMG_G21,
                              IMG_G22, IMG_D1, IMG_D2, IMG_F1, IMG_F2};

    __shared__ float tile[32][129];

    int blk = blockIdx.x;
    int wi = 0;
    #pragma unroll
    for (int i = 0; i < 10; i++)
        if (blk >= WCUM[i] && blk < WCUM[i + 1]) wi = i;
    int local = blk - WCUM[wi];
    int nslab = WNS[wi];
    int nt = local / nslab, s = local - nt * nslab;
    int K = WK[wi], N = WN[wi];

    const float* W;
    switch (wi) {
        case 0: W = w0; break; case 1: W = w1; break; case 2: W = w2; break;
        case 3: W = w3; break; case 4: W = w4; break; case 5: W = w5; break;
        case 6: W = w6; break; case 7: W = w7; break; case 8: W = w8; break;
        default: W = w9; break;
    }

    int tid = threadIdx.x;
    int nc = tid & 127, kq = tid >> 7;
    #pragma unroll
    for (int i = 0; i < 16; i++) {
        int k = kq + i * 2;
        int gk = s * 32 + k, gn = nt * 128 + nc;
        float v = (gk < K && gn < N) ? W[(size_t)gk * N + gn] : 0.f;
        tile[k][nc] = v;
    }
    __syncthreads();

    char* hb = (char*)(hi + WIOF[wi]) + (size_t)local * 10240;
    char* lb = (char*)(lo + WIOF[wi]) + (size_t)local * 10240;
    #pragma unroll
    for (int it = 0; it < 2; it++) {
        int idx = tid + it * 256;
        int n = idx >> 2, q = idx & 3;
        uint32_t h[4], l[4];
        #pragma unroll
        for (int j = 0; j < 4; j++) {
            float f0 = tile[q * 8 + 2 * j][n];
            float f1 = tile[q * 8 + 2 * j + 1][n];
            float h0 = __bfloat162float(__float2bfloat16(f0));
            float h1 = __bfloat162float(__float2bfloat16(f1));
            h[j] = packbf(f0, f1);
            l[j] = packbf(f0 - h0, f1 - h1);
        }
        *(uint4*)(hb + n * 80 + q * 16) = make_uint4(h[0], h[1], h[2], h[3]);
        *(uint4*)(lb + n * 80 + q * 16) = make_uint4(l[0], l[1], l[2], l[3]);
    }
}

// ---------------------------------------------------------------------------
// Templated fused tensor-core GEMM (mma.sync bf16 split-3, fp32 accum):
//   C = EPI_ACT( IN_ACT(BN(A)) @ W + bias )
//   STAT_PRE: stats over relu(C);  POOL: per-graph max -> pmax, no C store
//   AGGE: GIN aggregation fused into EPILOGUE via (I+Adj)(yW) = ((I+Adj)y)W
//   FININ: BN mrs computed inline in smem from raw fp64 sums (small grids only)
// IN_ACT: 0 none, 1 BN->relu, 2 BN->elu, 3 relu->BN
// ---------------------------------------------------------------------------
#define TG_SMEM 81920

template<int IN_ACT, int EPI_ACT, int STAT_PRE, int POOL, int AGGE, int FININ>
__global__ __launch_bounds__(256, 2)
void tgemm(const float* __restrict__ A, int lda, int Korig, int nslab,
           const __nv_bfloat16* __restrict__ Whi, const __nv_bfloat16* __restrict__ Wlo,
           const float* __restrict__ bias,
           float* __restrict__ C, int ldc, int N,
           const float2* __restrict__ mrsIn,
           const double* __restrict__ inSum, const double* __restrict__ inSq, int inM,
           double* __restrict__ stSum, double* __restrict__ stSq,
           float* __restrict__ pmax,
           const int* __restrict__ srcE, const int* __restrict__ dstE)
{
    extern __shared__ char dynsm[];
    __shared__ float ssum[128], ssq[128];
    __shared__ uint32_t pmS[POOL ? 512 : 1];
    __shared__ int lsE[AGGE ? 256 : 1], ldE[AGGE ? 256 : 1];
    __shared__ float2 mrsS[FININ ? 128 : 1];

    const int tid = threadIdx.x;
    const int wid = tid >> 5, lane = tid & 31;
    const int mt = blockIdx.y, ntile = blockIdx.x;
    const int bn0 = ntile * 128;

    const float* Ab = A + (size_t)mt * 128 * lda;
    const char* BHall = (const char*)Whi + (size_t)ntile * nslab * 10240;
    const char* BLall = (const char*)Wlo + (size_t)ntile * nslab * 10240;

    const uint32_t smu = s2u(dynsm);
    const int wm = (wid >> 2) * 64, wn = (wid & 3) * 32;

    if (AGGE) {
        lsE[tid] = srcE[mt * 256 + tid] & (NPG - 1);
        ldE[tid] = dstE[mt * 256 + tid] & (NPG - 1);
    }
    if (FININ) {
        if (tid < 128) mrsS[tid] = mrs_of(inSum, inSq, tid, 1.f / (float)inM);
        __syncthreads();
    }
    const float2* __restrict__ mrsP = FININ ? (const float2*)mrsS : mrsIn;

    float acc[4][4][4];
    #pragma unroll
    for (int a = 0; a < 4; a++)
        #pragma unroll
        for (int b = 0; b < 4; b++)
            #pragma unroll
            for (int c = 0; c < 4; c++) acc[a][b][c] = 0.f;

    float4 av[4];

    auto bload = [&](int s) {
        uint32_t st = (uint32_t)(s & 1) * 10240u;
        uint32_t dh = smu + 40960 + st, dl = smu + 61440 + st;
        const char* sh = BHall + (size_t)s * 10240;
        const char* sl = BLall + (size_t)s * 10240;
        #pragma unroll
        for (int i = tid; i < 640; i += 256) {
            cpasync16(dh + i * 16, sh + i * 16);
            cpasync16(dl + i * 16, sl + i * 16);
        }
        CP_COMMIT();
    };

    auto gload = [&](int s) {
        int k0 = s * 32;
        #pragma unroll
        for (int j = 0; j < 4; j++) {
            int f = tid + 256 * j;
            int r = f >> 3, c4 = f & 7;
            int kc = k0 + c4 * 4;
            const float* ap = Ab + (size_t)r * lda + kc;
            if (kc + 3 < Korig) {
                av[j] = *(const float4*)ap;
            } else {
                av[j].x = (kc + 0 < Korig) ? ap[0] : 0.f;
                av[j].y = (kc + 1 < Korig) ? ap[1] : 0.f;
                av[j].z = (kc + 2 < Korig) ? ap[2] : 0.f;
                av[j].w = (kc + 3 < Korig) ? ap[3] : 0.f;
            }
        }
    };

    auto convstore = [&](int s) {
        uint32_t st = (uint32_t)(s & 1) * 10240u;
        char* AH = dynsm + st;
        char* AL = dynsm + 20480 + st;
        int k0 = s * 32;
        #pragma unroll
        for (int j = 0; j < 4; j++) {
            int f = tid + 256 * j;
            int r = f >> 3, c4 = f & 7;
            float4 v = av[j];
            if (IN_ACT != 0) {
                int kc = k0 + c4 * 4;
                float2 p0 = mrsP[kc + 0], p1 = mrsP[kc + 1];
                float2 p2 = mrsP[kc + 2], p3 = mrsP[kc + 3];
                if (IN_ACT == 3) {
                    v.x = (fmaxf(v.x, 0.f) - p0.x) * p0.y;
                    v.y = (fmaxf(v.y, 0.f) - p1.x) * p1.y;
                    v.z = (fmaxf(v.z, 0.f) - p2.x) * p2.y;
                    v.w = (fmaxf(v.w, 0.f) - p3.x) * p3.y;
                } else {
                    v.x = (v.x - p0.x) * p0.y;
                    v.y = (v.y - p1.x) * p1.y;
                    v.z = (v.z - p2.x) * p2.y;
                    v.w = (v.w - p3.x) * p3.y;
                    if (IN_ACT == 1) {
                        v.x = fmaxf(v.x, 0.f); v.y = fmaxf(v.y, 0.f);
                        v.z = fmaxf(v.z, 0.f); v.w = fmaxf(v.w, 0.f);
                    } else if (IN_ACT == 2) {
                        v.x = (v.x > 0.f) ? v.x : expm1f(v.x);
                        v.y = (v.y > 0.f) ? v.y : expm1f(v.y);
                        v.z = (v.z > 0.f) ? v.z : expm1f(v.z);
                        v.w = (v.w > 0.f) ? v.w : expm1f(v.w);
                    }
                }
            }
            float hx = __bfloat162float(__float2bfloat16(v.x));
            float hy = __bfloat162float(__float2bfloat16(v.y));
            float hz = __bfloat162float(__float2bfloat16(v.z));
            float hw = __bfloat162float(__float2bfloat16(v.w));
            uint2 h2, l2;
            h2.x = packbf(v.x, v.y);  h2.y = packbf(v.z, v.w);
            l2.x = packbf(v.x - hx, v.y - hy);
            l2.y = packbf(v.z - hz, v.w - hw);
            uint32_t off = (uint32_t)(r * 80 + c4 * 8);
            *(uint2*)(AH + off) = h2;
            *(uint2*)(AL + off) = l2;
        }
    };

    auto mma_slab = [&](int s) {
        uint32_t st = (uint32_t)(s & 1) * 10240u;
        uint32_t AHb = smu + st, ALb = smu + 20480 + st;
        uint32_t BHb = smu + 40960 + st, BLb = smu + 61440 + st;
        #pragma unroll
        for (int kk = 0; kk < 2; kk++) {
            uint32_t bh[4][2], bl[4][2];
            #pragma unroll
            for (int ni2 = 0; ni2 < 2; ni2++) {
                int n0 = wn + ni2 * 16 + ((lane >> 4) << 3) + (lane & 7);
                uint32_t off = (uint32_t)(n0 * 40 + kk * 16 + ((lane >> 3) & 1) * 8) * 2;
                uint32_t t4[4];
                ldsm4(t4, BHb + off);
                bh[2 * ni2][0] = t4[0]; bh[2 * ni2][1] = t4[1];
                bh[2 * ni2 + 1][0] = t4[2]; bh[2 * ni2 + 1][1] = t4[3];
                ldsm4(t4, BLb + off);
                bl[2 * ni2][0] = t4[0]; bl[2 * ni2][1] = t4[1];
                bl[2 * ni2 + 1][0] = t4[2]; bl[2 * ni2 + 1][1] = t4[3];
            }
            #pragma unroll
            for (int mi = 0; mi < 4; mi++) {
                int row = wm + mi * 16 + (lane & 15);
                uint32_t off = (uint32_t)(row * 40 + kk * 16 + (lane >> 4) * 8) * 2;
                uint32_t ah[4], al[4];
                ldsm4(ah, AHb + off);
                ldsm4(al, ALb + off);
                #pragma unroll
                for (int ni = 0; ni < 4; ni++) {
                    mma16816(acc[mi][ni], ah, bh[ni]);
                    mma16816(acc[mi][ni], ah, bl[ni]);
                    mma16816(acc[mi][ni], al, bh[ni]);
                }
            }
        }
    };

    // ---- pipelined mainloop ----
    bload(0);
    gload(0);
    convstore(0);
    CP_WAIT0();
    __syncthreads();
    for (int s = 0; s < nslab; s++) {
        bool more = (s + 1 < nslab);
        if (more) { bload(s + 1); gload(s + 1); }
        mma_slab(s);
        if (more) { convstore(s + 1); CP_WAIT0(); }
        __syncthreads();
    }

    // ---- epilogue ----
    bool hasStats = (stSum != nullptr);
    if (hasStats && tid < 128) { ssum[tid] = 0.f; ssq[tid] = 0.f; }
    if (POOL) { pmS[tid] = 0u; pmS[tid + 256] = 0u; }
    __syncthreads();

    if (AGGE) {
        // out = u + Adj.u + bias, u = raw GEMM result; 2 phases of 64 rows
        float* u2 = (float*)dynsm;              // 64 x 129 floats
        float* ag = (float*)(dynsm + 33024);    // 64 x 129 floats
        const int gph = tid >> 7;               // graph within phase (0/1)
        const int cc  = tid & 127;
        const float bv = bias[cc];
        #pragma unroll
        for (int ph = 0; ph < 2; ph++) {
            if ((wid >> 2) == ph) {
                #pragma unroll
                for (int ni = 0; ni < 4; ni++) {
                    int lc0 = wn + ni * 8 + 2 * (lane & 3);
                    #pragma unroll
                    for (int mi = 0; mi < 4; mi++) {
                        int lr = mi * 16 + (lane >> 2);
                        u2[lr * 129 + lc0]           = acc[mi][ni][0];
                        u2[lr * 129 + lc0 + 1]       = acc[mi][ni][1];
                        u2[(lr + 8) * 129 + lc0]     = acc[mi][ni][2];
                        u2[(lr + 8) * 129 + lc0 + 1] = acc[mi][ni][3];
                    }
                }
            }
            __syncthreads();
            int rb = gph * 32;
            #pragma unroll 4
            for (int r = 0; r < 32; r++) ag[(rb + r) * 129 + cc] = 0.f;
            int eb = (ph * 2 + gph) * 64;
            for (int e = 0; e < 64; e++)
                ag[(rb + ldE[eb + e]) * 129 + cc] += u2[(rb + lsE[eb + e]) * 129 + cc];
            float s1 = 0.f, s2 = 0.f;
            #pragma unroll 4
            for (int r = 0; r < 32; r++) {
                float o = u2[(rb + r) * 129 + cc] + ag[(rb + r) * 129 + cc] + bv;
                C[(size_t)(mt * 128 + ph * 64 + rb + r) * ldc + cc] = o;
                s1 += o; s2 += o * o;
            }
            atomicAdd(&ssum[cc], s1);
            atomicAdd(&ssq[cc], s2);
            __syncthreads();
        }
    } else {
        #pragma unroll
        for (int ni = 0; ni < 4; ni++) {
            float ps0 = 0.f, ps1 = 0.f, pq0 = 0.f, pq1 = 0.f;
            int lc0 = wn + ni * 8 + 2 * (lane & 3);
            int gc0 = bn0 + lc0;
            float b0v = (gc0 < N) ? bias[gc0] : 0.f;
            float b1v = (gc0 + 1 < N) ? bias[gc0 + 1] : 0.f;
            #pragma unroll
            for (int mi = 0; mi < 4; mi++) {
                float v00 = acc[mi][ni][0] + b0v, v01 = acc[mi][ni][1] + b1v;
                float v10 = acc[mi][ni][2] + b0v, v11 = acc[mi][ni][3] + b1v;
                int lr0 = wm + mi * 16 + (lane >> 2);
                if (hasStats) {
                    float s00 = STAT_PRE ? fmaxf(v00, 0.f) : v00;
                    float s01 = STAT_PRE ? fmaxf(v01, 0.f) : v01;
                    float s10 = STAT_PRE ? fmaxf(v10, 0.f) : v10;
                    float s11 = STAT_PRE ? fmaxf(v11, 0.f) : v11;
                    ps0 += s00 + s10;  ps1 += s01 + s11;
                    pq0 += s00 * s00 + s10 * s10;
                    pq1 += s01 * s01 + s11 * s11;
                }
                if (POOL) {
                    atomicMax(&pmS[(lr0 >> 5) * 128 + lc0],           encf(v00));
                    atomicMax(&pmS[(lr0 >> 5) * 128 + lc0 + 1],       encf(v01));
                    atomicMax(&pmS[((lr0 + 8) >> 5) * 128 + lc0],     encf(v10));
                    atomicMax(&pmS[((lr0 + 8) >> 5) * 128 + lc0 + 1], encf(v11));
                } else if (gc0 < N) {
                    float o00 = v00, o01 = v01, o10 = v10, o11 = v11;
                    if (EPI_ACT == 1) {
                        o00 = fmaxf(o00, 0.f); o01 = fmaxf(o01, 0.f);
                        o10 = fmaxf(o10, 0.f); o11 = fmaxf(o11, 0.f);
                    }
                    int r0 = mt * 128 + lr0;
                    *(float2*)&C[(size_t)r0 * ldc + gc0]       = make_float2(o00, o01);
                    *(float2*)&C[(size_t)(r0 + 8) * ldc + gc0] = make_float2(o10, o11);
                }
            }
            if (hasStats) {
                #pragma unroll
                for (int off = 16; off >= 4; off >>= 1) {
                    ps0 += __shfl_xor_sync(0xffffffffu, ps0, off);
                    ps1 += __shfl_xor_sync(0xffffffffu, ps1, off);
                    pq0 += __shfl_xor_sync(0xffffffffu, pq0, off);
                    pq1 += __shfl_xor_sync(0xffffffffu, pq1, off);
                }
                if (lane < 4) {
                    int lc = wn + ni * 8 + 2 * lane;
                    atomicAdd(&ssum[lc], ps0);     atomicAdd(&ssq[lc], pq0);
                    atomicAdd(&ssum[lc + 1], ps1); atomicAdd(&ssq[lc + 1], pq1);
                }
            }
        }
    }
    __syncthreads();
    if (hasStats && tid < 128 && bn0 + tid < N) {
        atomicAdd(&stSum[bn0 + tid], (double)ssum[tid]);
        atomicAdd(&stSq[bn0 + tid],  (double)ssq[tid]);
    }
    if (POOL) {
        #pragma unroll
        for (int i = tid; i < 512; i += 256) {
            int g = mt * 4 + (i >> 7);
            pmax[(size_t)g * 128 + (i & 127)] = decf(pmS[i]);
        }
    }
}

// ---------------------------------------------------------------------------
// BN helper kernels
// ---------------------------------------------------------------------------
__global__ void init_misc(double* stats, float2* ident) {
    int i = blockIdx.x * blockDim.x + threadIdx.x;
    if (i < 2 * STATS_N + 2 * G1B_N) stats[i] = 0.0;
    if (i < 128) ident[i] = make_float2(0.f, 1.f);
}

__global__ void bn_finalize(const double* __restrict__ sum, const double* __restrict__ sumsq,
                            float2* __restrict__ mrs, int C, int M)
{
    int c = blockIdx.x * blockDim.x + threadIdx.x;
    if (c >= C) return;
    double m = sum[c] / (double)M;
    double v = sumsq[c] / (double)M - m * m;
    mrs[c] = make_float2((float)m, rsqrtf((float)v + BN_EPS));
}

__global__ void bn_finalize_g1(const double* __restrict__ bsum,
                               const double* __restrict__ bsq,
                               float2* __restrict__ mrs)
{
    int c = threadIdx.x;
    double s = 0.0, q = 0.0;
    #pragma unroll
    for (int b = 0; b < 32; b++) {
        s += bsum[b * 128 + c];
        q += bsq[b * 128 + c];
    }
    double m = s / (double)NNODES;
    double v = q / (double)NNODES - m * m;
    mrs[c] = make_float2((float)m, rsqrtf((float)v + BN_EPS));
}

// ---------------------------------------------------------------------------
// Graph kernels
// ---------------------------------------------------------------------------
// gin1 + bucketed stats; parallel edge aggregation via smem atomics
__global__ void gin1_fused(const float* __restrict__ X,
                           const int* __restrict__ src, const int* __restrict__ dst,
                           const float* __restrict__ W, const float* __restrict__ b,
                           float* __restrict__ out,
                           double* __restrict__ bsum, double* __restrict__ bsq)
{
    __shared__ float xs[NPG][9];
    __shared__ float h0[NPG][9];
    __shared__ float Ws[9][128];
    __shared__ float bsh[128];
    __shared__ int   ls[EPG], ld[EPG];
    int g = blockIdx.x;
    int t = threadIdx.x;
    for (int i = t; i < NPG * 9; i += 128) {
        xs[i / 9][i % 9] = X[(size_t)g * NPG * 9 + i];
        h0[i / 9][i % 9] = 0.f;
    }
    if (t < EPG) {
        ls[t] = src[g * EPG + t] & (NPG - 1);
        ld[t] = dst[g * EPG + t] & (NPG - 1);
    }
    for (int i = t; i < 9 * 128; i += 128) Ws[i / 128][i % 128] = W[i];
    bsh[t] = b[t];
    __syncthreads();
    // parallel edge aggregation: 576 (edge, feature) items over 128 threads
    for (int i = t; i < EPG * 9; i += 128) {
        int e = i / 9, c = i - e * 9;
        atomicAdd(&h0[ld[e]][c], xs[ls[e]][c]);
    }
    __syncthreads();
    for (int i = t; i < NPG * 9; i += 128) h0[i / 9][i % 9] += xs[i / 9][i % 9];
    __syncthreads();
    float s1 = 0.f, s2 = 0.f;
    for (int r = 0; r < NPG; r++) {
        float acc = bsh[t];
        #pragma unroll
        for (int k = 0; k < 9; k++) acc += h0[r][k] * Ws[k][t];
        out[((size_t)g * NPG + r) * 128 + t] = acc;
        s1 += acc; s2 += acc * acc;
    }
    int bkt = (g & 31) * 128 + t;
    atomicAdd(&bsum[bkt], (double)s1);
    atomicAdd(&bsq[bkt],  (double)s2);
}

// y[i] = dot(elu(BN(Z[i,:])), w) + b; BN finalize inline from sums
__global__ void final_dot(const float* __restrict__ Z,
                          const double* __restrict__ sum, const double* __restrict__ sq,
                          const float* __restrict__ w, const float* __restrict__ b,
                          float* __restrict__ y, int Bn)
{
    int warp = (blockIdx.x * blockDim.x + threadIdx.x) >> 5;
    int lane = threadIdx.x & 31;
    if (warp >= Bn) return;
    float invM = 1.f / (float)BATCH;
    float2 p0 = mrs_of(sum, sq, lane, invM);
    float2 p1 = mrs_of(sum, sq, 32 + lane, invM);
    float x0 = (Z[(size_t)warp * 64 + lane]      - p0.x) * p0.y;
    float x1 = (Z[(size_t)warp * 64 + 32 + lane] - p1.x) * p1.y;
    x0 = (x0 > 0.f) ? x0 : expm1f(x0);
    x1 = (x1 > 0.f) ? x1 : expm1f(x1);
    float s = x0 * w[lane] + x1 * w[32 + lane];
    #pragma unroll
    for (int o = 16; o; o >>= 1) s += __shfl_down_sync(0xffffffffu, s, o);
    if (lane == 0) y[warp] = s + b[0];
}

// ---------------------------------------------------------------------------
// Host side
// ---------------------------------------------------------------------------
template<int IA, int EA, int SP, int PL, int AG, int FI>
static inline void run_tg(cudaStream_t st, const float* A, int lda, int Korig, int nslab,
                          const __nv_bfloat16* wh, const __nv_bfloat16* wl,
                          const float* bias, float* C, int ldc, int N,
                          const float2* mrs,
                          const double* inSum, const double* inSq, int inM,
                          double* ss, double* sq2,
                          float* pmax, const int* srcE, const int* dstE, int M)
{
    cudaFuncSetAttribute(tgemm<IA, EA, SP, PL, AG, FI>,
                         cudaFuncAttributeMaxDynamicSharedMemorySize, TG_SMEM);
    dim3 g((N + 127) / 128, M / 128);
    tgemm<IA, EA, SP, PL, AG, FI><<<g, 256, TG_SMEM, st>>>(
        A, lda, Korig, nslab, wh, wl, bias, C, ldc, N,
        mrs, inSum, inSq, inM, ss, sq2, pmax, srcE, dstE);
}

extern "C" void kernel_launch(void* const* d_in, const int* in_sizes, int n_in,
                              void* d_out, int out_size)
{
    (void)in_sizes; (void)n_in; (void)out_size;
    const float* cell    = (const float*)d_in[0];
    const float* drug_x  = (const float*)d_in[1];
    const int*   eidx    = (const int*)  d_in[2];
    const float* ce1w = (const float*)d_in[4];  const float* ce1b = (const float*)d_in[5];
    const float* ce2w = (const float*)d_in[6];  const float* ce2b = (const float*)d_in[7];
    const float* ce3w = (const float*)d_in[8];  const float* ce3b = (const float*)d_in[9];
    const float* g11w = (const float*)d_in[10]; const float* g11b = (const float*)d_in[11];
    const float* g12w = (const float*)d_in[12]; const float* g12b = (const float*)d_in[13];
    const float* g21w = (const float*)d_in[14]; const float* g21b = (const float*)d_in[15];
    const float* g22w = (const float*)d_in[16]; const float* g22b = (const float*)d_in[17];
    const float* d1w  = (const float*)d_in[18]; const float* d1b  = (const float*)d_in[19];
    const float* d2w  = (const float*)d_in[20]; const float* d2b  = (const float*)d_in[21];
    const float* f1w  = (const float*)d_in[22]; const float* f1b  = (const float*)d_in[23];
    const float* f2w  = (const float*)d_in[24]; const float* f2b  = (const float*)d_in[25];
    const float* f3w  = (const float*)d_in[26]; const float* f3b  = (const float*)d_in[27];

    const int* src = eidx;
    const int* dst = eidx + NEDGES;
    float* out = (float*)d_out;

    float *A, *Bf, *c1, *c2, *z, *p, *q, *f2buf;
    double* stats;
    float2* mrs;
    __nv_bfloat16 *whi, *wlo;
    cudaGetSymbolAddress((void**)&A,     g_A);
    cudaGetSymbolAddress((void**)&Bf,    g_Bf);
    cudaGetSymbolAddress((void**)&c1,    g_c1);
    cudaGetSymbolAddress((void**)&c2,    g_c2);
    cudaGetSymbolAddress((void**)&z,     g_z);
    cudaGetSymbolAddress((void**)&p,     g_p);
    cudaGetSymbolAddress((void**)&q,     g_q);
    cudaGetSymbolAddress((void**)&f2buf, g_f2);
    cudaGetSymbolAddress((void**)&stats, g_stats);
    cudaGetSymbolAddress((void**)&mrs,   g_mrs);
    cudaGetSymbolAddress((void**)&whi,   g_whi);
    cudaGetSymbolAddress((void**)&wlo,   g_wlo);
    double* sum   = stats;
    double* sq    = stats + STATS_N;
    double* g1bs  = stats + 2 * STATS_N;
    double* g1bq  = stats + 2 * STATS_N + G1B_N;

    // ---- prologue: init on NULL; wconv on s2 (overlaps gin1_fused) ----
    init_misc<<<(2 * STATS_N + 2 * G1B_N + 255) / 256, 256>>>(stats, mrs + OFF_F1CAT + 128);
    cudaEventRecord(g_ev1, 0);
    cudaStreamWaitEvent(g_s2, g_ev1, 0);

    wconv_all<<<219, 256, 0, g_s2>>>(ce1w, ce2w, ce3w, g12w, g21w, g22w,
                                     d1w, d2w, f1w, f2w, whi, wlo);
    cudaEventRecord(g_ev3, g_s2);   // weight images ready

    // ---- cell branch continues on s2 ----
    run_tg<0,0,0,0,0,0>(g_s2, cell, CELLD, CELLD, 29, whi + IMG_CE1, wlo + IMG_CE1, ce1b,
                        c1, 516, 516, nullptr, nullptr, nullptr, 1,
                        sum + OFF_CE1, sq + OFF_CE1, nullptr, nullptr, nullptr, BATCH);
    bn_finalize<<<5, 128, 0, g_s2>>>(sum + OFF_CE1, sq + OFF_CE1, mrs + OFF_CE1, 516, BATCH);
    run_tg<1,0,0,0,0,0>(g_s2, c1, 516, 516, 17, whi + IMG_CE2, wlo + IMG_CE2, ce2b,
                        c2, 256, 256, mrs + OFF_CE1, nullptr, nullptr, 1,
                        sum + OFF_CE2, sq + OFF_CE2, nullptr, nullptr, nullptr, BATCH);
    bn_finalize<<<2, 128, 0, g_s2>>>(sum + OFF_CE2, sq + OFF_CE2, mrs + OFF_CE2, 256, BATCH);
    run_tg<1,0,0,0,0,0>(g_s2, c2, 256, 256, 8, whi + IMG_CE3, wlo + IMG_CE3, ce3b,
                        z, 256, 128, mrs + OFF_CE2, nullptr, nullptr, 1,
                        sum + OFF_CE3, sq + OFF_CE3, nullptr, nullptr, nullptr, BATCH);
    bn_finalize<<<1, 128, 0, g_s2>>>(sum + OFF_CE3, sq + OFF_CE3, mrs + OFF_F1CAT, 128, BATCH);
    cudaEventRecord(g_ev2, g_s2);

    // ---- GIN chain (NULL stream); gin1 overlaps wconv ----
    gin1_fused<<<BATCH, 128>>>(drug_x, src, dst, g11w, g11b, A, g1bs, g1bq);
    bn_finalize_g1<<<1, 128>>>(g1bs, g1bq, mrs + OFF_G1A);
    cudaStreamWaitEvent(0, g_ev3, 0);   // need weight images from here on
    run_tg<1,0,1,0,0,0>(0, A, 128, 128, 4, whi + IMG_G12, wlo + IMG_G12, g12b,
                        Bf, 128, 128, mrs + OFF_G1A, nullptr, nullptr, 1,
                        sum + OFF_G1B, sq + OFF_G1B, nullptr, nullptr, nullptr, NNODES);
    bn_finalize<<<1, 128>>>(sum + OFF_G1B, sq + OFF_G1B, mrs + OFF_G1B, 128, NNODES);

    // G21: AGGE — loader relu->BN on raw G12 out; epilogue applies (I+Adj) + bias
    run_tg<3,0,0,0,1,0>(0, Bf, 128, 128, 4, whi + IMG_G21, wlo + IMG_G21, g21b,
                        A, 128, 128, mrs + OFF_G1B, nullptr, nullptr, 1,
                        sum + OFF_G2A, sq + OFF_G2A, nullptr, src, dst, NNODES);
    bn_finalize<<<1, 128>>>(sum + OFF_G2A, sq + OFF_G2A, mrs + OFF_G2A, 128, NNODES);
    // G22: POOL — no C store; per-graph max -> p; stats over relu(h)
    run_tg<1,0,1,1,0,0>(0, A, 128, 128, 4, whi + IMG_G22, wlo + IMG_G22, g22b,
                        nullptr, 128, 128, mrs + OFF_G2A, nullptr, nullptr, 1,
                        sum + OFF_G2B, sq + OFF_G2B, p, nullptr, nullptr, NNODES);

    // ---- drug head (pooled; D1 FININ finalizes G2B inline; relu->BN) ----
    run_tg<3,0,0,0,0,1>(0, p, 128, 128, 4, whi + IMG_D1, wlo + IMG_D1, d1b,
                        q, 128, 128, nullptr, sum + OFF_G2B, sq + OFF_G2B, NNODES,
                        sum + OFF_D1, sq + OFF_D1, nullptr, nullptr, nullptr, BATCH);
    // D2: FININ finalizes D1 inline; BN->relu input, relu epilogue
    run_tg<1,1,0,0,0,1>(0, q, 128, 128, 4, whi + IMG_D2, wlo + IMG_D2, d2b,
                        z + 128, 256, 128, nullptr, sum + OFF_D1, sq + OFF_D1, BATCH,
                        nullptr, nullptr, nullptr, nullptr, nullptr, BATCH);

    // ---- join: wait for cell branch, then fusion head ----
    cudaStreamWaitEvent(0, g_ev2, 0);
    run_tg<1,0,0,0,0,0>(0, z, 256, 256, 8, whi + IMG_F1, wlo + IMG_F1, f1b,
                        q, 128, 128, mrs + OFF_F1CAT, nullptr, nullptr, 1,
                        sum + OFF_F1, sq + OFF_F1, nullptr, nullptr, nullptr, BATCH);
    // F2: FININ finalizes F1 inline; BN->elu input
    run_tg<2,0,0,0,0,1>(0, q, 128, 128, 4, whi + IMG_F2, wlo + IMG_F2, f2b,
                        f2buf, 64, 64, nullptr, sum + OFF_F1, sq + OFF_F1, BATCH,
                        sum + OFF_F2, sq + OFF_F2, nullptr, nullptr, nullptr, BATCH);
    final_dot<<<(BATCH * 32 + 255) / 256, 256>>>(f2buf, sum + OFF_F2, sq + OFF_F2,
                                                 f3w, f3b, out, BATCH);
}